// round 13
// baseline (speedup 1.0000x reference)
#include <cuda_runtime.h>

// ============================================================================
// EnasController R13: R9 base (best known: 55.3us) + balanced anchor phase
// ONLY (w2out spread 4 threads/row over all 8 warps, removing the 1-dot
// convoy imbalance on warps 6-7). Everything else identical to R9.
// 256 threads; wh0/wh1/wi1 register-resident; PA rank reduction; deferred stats.
// ============================================================================

#define N_LAYERS 12
#define NB 6
#define HID 64
#define PAD 68

typedef unsigned long long u64;

// ---- shared memory layout (float offsets) ----
#define OF_WI0   0                        // 256*68
#define OF_WAT2  (OF_WI0 + 256*PAD)       // 64*68
#define OF_WSOFT (OF_WAT2 + 64*PAD)       // 384
#define OF_VATTN (OF_WSOFT + 384)         // 64
#define OF_WEMB  (OF_VATTN + 64)          // 384
#define OF_GEMB  (OF_WEMB + 384)          // 64
#define OF_P     (OF_GEMB + 64)           // 7*256  (t-indexed)
#define OF_PA    (OF_P + 7*256)           // 12*256 (t-indexed)
#define OF_H0A   (OF_PA + 12*256)
#define OF_H0B   (OF_H0A + 64)
#define OF_H1A   (OF_H0B + 64)
#define OF_H1B   (OF_H1A + 64)
#define OF_AW1   (OF_H1B + 64)            // 12*64
#define OF_W2OUT (OF_AW1 + 768)           // 64
#define OF_QVS   (OF_W2OUT + 64)          // 12*16
#define OF_LOGS  (OF_QVS + 192)           // 12*8
#define OF_GUMB  (OF_LOGS + 96)           // 12*8 (stride 8)
#define OF_GUMS  (OF_GUMB + 96)           // 136
#define OF_BLP   (OF_GUMS + 136)          // 12
#define OF_BENT  (OF_BLP + 12)            // 12
#define OF_SLP   (OF_BENT + 12)           // 68
#define OF_SENT  (OF_SLP + 68)            // 68
#define OF_SKL   (OF_SENT + 68)           // 68
#define OF_SKF   (OF_SKL + 68)            // 16
#define OF_IREG  (OF_SKF + 16)
#define SMEM_FLOATS (OF_IREG + 80)
#define SMEM_BYTES  (SMEM_FLOATS * 4)
#define IO_LKEY  0
#define IO_KB    24
#define IO_KS    48

#define FMA2(acc, w, x) \
    asm("fma.rn.f32x2 %0, %1, %2, %0;" : "+l"(acc) : "l"(w), "l"(x))

__device__ __forceinline__ float lo32(u64 v) { return __uint_as_float((unsigned)v); }
__device__ __forceinline__ float hi32(u64 v) { return __uint_as_float((unsigned)(v >> 32)); }

__device__ __forceinline__ unsigned rotl32(unsigned x, int r) {
    return (x << r) | (x >> (32 - r));
}

__device__ __forceinline__ void tf2x32(unsigned k0, unsigned k1,
                                       unsigned x0, unsigned x1,
                                       unsigned &o0, unsigned &o1) {
    const unsigned ks2 = k0 ^ k1 ^ 0x1BD11BDAu;
    x0 += k0; x1 += k1;
    x0+=x1; x1=rotl32(x1,13); x1^=x0;
    x0+=x1; x1=rotl32(x1,15); x1^=x0;
    x0+=x1; x1=rotl32(x1,26); x1^=x0;
    x0+=x1; x1=rotl32(x1, 6); x1^=x0;
    x0+=k1; x1+=ks2+1u;
    x0+=x1; x1=rotl32(x1,17); x1^=x0;
    x0+=x1; x1=rotl32(x1,29); x1^=x0;
    x0+=x1; x1=rotl32(x1,16); x1^=x0;
    x0+=x1; x1=rotl32(x1,24); x1^=x0;
    x0+=ks2; x1+=k0+2u;
    x0+=x1; x1=rotl32(x1,13); x1^=x0;
    x0+=x1; x1=rotl32(x1,15); x1^=x0;
    x0+=x1; x1=rotl32(x1,26); x1^=x0;
    x0+=x1; x1=rotl32(x1, 6); x1^=x0;
    x0+=k0; x1+=k1+3u;
    x0+=x1; x1=rotl32(x1,17); x1^=x0;
    x0+=x1; x1=rotl32(x1,29); x1^=x0;
    x0+=x1; x1=rotl32(x1,16); x1^=x0;
    x0+=x1; x1=rotl32(x1,24); x1^=x0;
    x0+=k1; x1+=ks2+4u;
    x0+=x1; x1=rotl32(x1,13); x1^=x0;
    x0+=x1; x1=rotl32(x1,15); x1^=x0;
    x0+=x1; x1=rotl32(x1,26); x1^=x0;
    x0+=x1; x1=rotl32(x1, 6); x1^=x0;
    x0+=ks2; x1+=k0+5u;
    o0 = x0; o1 = x1;
}

__device__ __forceinline__ unsigned rbits32(unsigned k0, unsigned k1, int idx) {
    unsigned o0, o1;
    tf2x32(k0, k1, 0u, (unsigned)idx, o0, o1);
    return o0 ^ o1;
}

__device__ __forceinline__ float gumbel_from_bits(unsigned bits) {
    const float TINY = 1.17549435e-38f;
    float f = __uint_as_float(0x3f800000u | (bits >> 9)) - 1.0f;
    float u = fmaxf(TINY, f + TINY);
    return -logf(-logf(u));
}

__device__ __forceinline__ float fsig(float x) {
    return __fdividef(1.0f, 1.0f + __expf(-x));
}
__device__ __forceinline__ float ftanh(float x) {
    float ax = fabsf(x);
    float e  = __expf(-2.0f * ax);
    float r  = __fdividef(1.0f - e, 1.0f + e);
    return copysignf(r, x);
}

__device__ __forceinline__ float dot64p(const ulonglong2* __restrict__ w,
                                        const ulonglong2* __restrict__ v) {
    u64 a0 = 0ull, a1 = 0ull, a2 = 0ull, a3 = 0ull;
#pragma unroll
    for (int k = 0; k < 16; k += 2) {
        ulonglong2 w0 = w[k], w1 = w[k + 1];
        ulonglong2 v0 = v[k], v1 = v[k + 1];
        FMA2(a0, w0.x, v0.x);
        FMA2(a1, w0.y, v0.y);
        FMA2(a2, w1.x, v1.x);
        FMA2(a3, w1.y, v1.y);
    }
    return ((lo32(a0) + hi32(a0)) + (lo32(a1) + hi32(a1)))
         + ((lo32(a2) + hi32(a2)) + (lo32(a3) + hi32(a3)));
}

__device__ __forceinline__ float dot64r(const u64* __restrict__ w,
                                        const ulonglong2* __restrict__ v) {
    u64 a0 = 0ull, a1 = 0ull, a2 = 0ull, a3 = 0ull;
#pragma unroll
    for (int k = 0; k < 16; k += 2) {
        ulonglong2 v0 = v[k], v1 = v[k + 1];
        FMA2(a0, w[2*k],     v0.x);
        FMA2(a1, w[2*k + 1], v0.y);
        FMA2(a2, w[2*k + 2], v1.x);
        FMA2(a3, w[2*k + 3], v1.y);
    }
    return ((lo32(a0) + hi32(a0)) + (lo32(a1) + hi32(a1)))
         + ((lo32(a2) + hi32(a2)) + (lo32(a3) + hi32(a3)));
}

// Epilogue: lane l holds pre-activation for gate (l>>3), row w*8+(l&7).
__device__ __forceinline__ void epi(float acc, float& c,
                                    float* __restrict__ hout,
                                    int l, int rowIdx) {
    int grp = l >> 3, r8 = l & 7;
    float act = (grp == 2) ? ftanh(acc) : fsig(acc);
    float ai = __shfl_sync(0xffffffffu, act, r8);
    float af = __shfl_sync(0xffffffffu, act, r8 + 8);
    float ag = __shfl_sync(0xffffffffu, act, r8 + 16);
    float ao = __shfl_sync(0xffffffffu, act, r8 + 24);
    float cn = af * c + ai * ag;
    c = cn;
    float hv = ao * ftanh(cn);
    if (l < 8) hout[rowIdx] = hv;
    __syncthreads();
}

__global__ __launch_bounds__(256, 1)
void enas_controller_kernel(const float* __restrict__ g_emb,
                            const float* __restrict__ w_emb,
                            const float* __restrict__ w_soft,
                            const float* __restrict__ w_attn2,
                            const float* __restrict__ v_attn,
                            const float* __restrict__ w_ih0,
                            const float* __restrict__ w_hh0,
                            const float* __restrict__ b_ih0,
                            const float* __restrict__ b_hh0,
                            const float* __restrict__ w_ih1,
                            const float* __restrict__ w_hh1,
                            const float* __restrict__ b_ih1,
                            const float* __restrict__ b_hh1,
                            const int* __restrict__ seed_p,
                            float* __restrict__ out3) {
    extern __shared__ __align__(16) float S[];
    unsigned* SI = (unsigned*)&S[OF_IREG];
    const int t = threadIdx.x;
    const int w = t >> 5, l = t & 31;
    const int grp = l >> 3, r8 = l & 7;
    const int rowIdx = w * 8 + r8;
    const int R = grp * 64 + rowIdx;

    // ---- stage weights into smem ----
    {
        const float4* g0 = (const float4*)w_ih0;
        for (int idx = t; idx < 256*16; idx += 256) {
            int row = idx >> 4, col = idx & 15;
            *(float4*)&S[OF_WI0 + row*PAD + col*4] = __ldg(&g0[idx]);
        }
        const float4* ga = (const float4*)w_attn2;
        for (int idx = t; idx < 64*16; idx += 256) {
            int row = idx >> 4, col = idx & 15;
            *(float4*)&S[OF_WAT2 + row*PAD + col*4] = __ldg(&ga[idx]);
        }
        const float4* gs = (const float4*)w_soft;
        if (t < NB*16) *(float4*)&S[OF_WSOFT + t*4] = __ldg(&gs[t]);
        const float4* ge = (const float4*)w_emb;
        if (t >= 32 && t < 32 + NB*16) *(float4*)&S[OF_WEMB + (t-32)*4] = __ldg(&ge[t-32]);
        if (t >= 128 && t < 144) *(float4*)&S[OF_GEMB + (t-128)*4] = __ldg(&((const float4*)g_emb)[t-128]);
        if (t >= 160 && t < 160 + HID) {
            S[OF_VATTN + t - 160] = __ldg(&v_attn[t - 160]);
            S[OF_H0A + t - 160] = 0.f;
            S[OF_H1A + t - 160] = 0.f;
        }
    }

    // ---- register weights: wh0, wh1, wi1 rows for gate row R ----
    u64 wh0[32], wh1[32], wi1[32];
    {
        const ulonglong2* p0 = (const ulonglong2*)(w_hh0 + R*HID);
        const ulonglong2* p1 = (const ulonglong2*)(w_hh1 + R*HID);
        const ulonglong2* p2 = (const ulonglong2*)(w_ih1 + R*HID);
#pragma unroll
        for (int k = 0; k < 16; k++) {
            ulonglong2 v0 = __ldg(&p0[k]);
            ulonglong2 v1 = __ldg(&p1[k]);
            ulonglong2 v2 = __ldg(&p2[k]);
            wh0[2*k] = v0.x; wh0[2*k + 1] = v0.y;
            wh1[2*k] = v1.x; wh1[2*k + 1] = v1.y;
            wi1[2*k] = v2.x; wi1[2*k + 1] = v2.y;
        }
    }
    const float b0R = __ldg(&b_ih0[R]) + __ldg(&b_hh0[R]);
    const float b1R = __ldg(&b_ih1[R]) + __ldg(&b_hh1[R]);

    // ---- RNG: serial key chain, then keys + all gumbels in parallel ----
    if (t == 0) {
        unsigned k0 = 0u, k1 = (unsigned)seed_p[0];
        for (int lid = 0; lid < N_LAYERS; lid++) {
            SI[IO_LKEY + 2*lid]     = k0;
            SI[IO_LKEY + 2*lid + 1] = k1;
            unsigned a0, a1;
            tf2x32(k0, k1, 0u, 0u, a0, a1);
            k0 = a0; k1 = a1;
        }
    }
    __syncthreads();
    if (t < 24) {
        int lid = t >> 1, which = t & 1;
        unsigned o0, o1;
        tf2x32(SI[IO_LKEY + 2*lid], SI[IO_LKEY + 2*lid + 1], 0u, (unsigned)(1 + which), o0, o1);
        int base = which ? IO_KS : IO_KB;
        SI[base + 2*lid] = o0; SI[base + 2*lid + 1] = o1;
    }
    // ---- P table (t-indexed) ----
    {
        const ulonglong2* wrow = (const ulonglong2*)&S[OF_WI0 + R*PAD];
#pragma unroll
        for (int b = 0; b < 7; b++) {
            const ulonglong2* vec = (const ulonglong2*)
                ((b < 6) ? &S[OF_WEMB + b*HID] : &S[OF_GEMB]);
            S[OF_P + b*256 + t] = b0R + dot64p(wrow, vec);
        }
    }
    __syncthreads();
    if (t < 72) {
        int lid = t / NB, j = t % NB;
        S[OF_GUMB + lid*8 + j] =
            gumbel_from_bits(rbits32(SI[IO_KB + 2*lid], SI[IO_KB + 2*lid + 1], j));
    } else if (t < 72 + 132) {
        int f = t - 72;
        int lid = 1;
        while (f >= lid*(lid+1)) lid++;
        int j = f - lid*(lid-1);
        S[OF_GUMS + f] =
            gumbel_from_bits(rbits32(SI[IO_KS + 2*lid], SI[IO_KS + 2*lid + 1], j));
    }
    __syncthreads();

    float c0 = 0.f, c1 = 0.f;

#pragma unroll 1
    for (int lid = 0; lid < N_LAYERS; ++lid) {
        // ===== phase 1: call1-cell0 (input via PA-sum for lid>=2) =====
        float sb1;
        {
            float acc;
            if (lid < 2) {
                acc = S[OF_P + 6*256 + t];
            } else {
                int nsk = lid - 1;
                float den = 1.0f, ps = 0.f;
                for (int i = 0; i < nsk; i++) {
                    float f = S[OF_SKF + i];
                    den += f;
                    ps = fmaf(f, S[OF_PA + i*256 + t], ps);
                }
                acc = b0R + __fdividef(ps, den);
            }
            acc += dot64r(wh0, (const ulonglong2*)&S[OF_H0A]);
            sb1 = dot64r(wh1, (const ulonglong2*)&S[OF_H1A]);
            epi(acc, c0, &S[OF_H0B], l, rowIdx);
        }
        // ===== phase 2: call1-cell1 =====
        {
            float sa = dot64r(wi1, (const ulonglong2*)&S[OF_H0B]);
            float acc = b1R + (sa + sb1);
            epi(acc, c1, &S[OF_H1B], l, rowIdx);
        }
        // ===== phase 3 (fused logits + call2-cell0) =====
        float sb1b;
        {
            if (t < 64) {
                int j = t >> 3, k0 = t & 7;
                int jc = (j < NB) ? j : 0;
                const float4* wv = (const float4*)&S[OF_WSOFT + jc*HID + k0*8];
                const float4* hv = (const float4*)&S[OF_H1B + k0*8];
                float4 wa = wv[0], wb = wv[1];
                float4 ha = hv[0], hb = hv[1];
                float s = wa.x*ha.x + wa.y*ha.y + wa.z*ha.z + wa.w*ha.w
                        + wb.x*hb.x + wb.y*hb.y + wb.z*hb.z + wb.w*hb.w;
                s += __shfl_down_sync(0xffffffffu, s, 4, 8);
                s += __shfl_down_sync(0xffffffffu, s, 2, 8);
                s += __shfl_down_sync(0xffffffffu, s, 1, 8);
                if (k0 == 0 && j < NB) S[OF_LOGS + lid*8 + j] = s;
            }
            float pre4 = dot64r(wh0, (const ulonglong2*)&S[OF_H0B]);
            sb1b = dot64r(wh1, (const ulonglong2*)&S[OF_H1B]);
            __syncthreads();

            float4 la = *(const float4*)&S[OF_LOGS + lid*8];
            float4 lb = *(const float4*)&S[OF_LOGS + lid*8 + 4];
            float4 ga = *(const float4*)&S[OF_GUMB + lid*8];
            float4 gb = *(const float4*)&S[OF_GUMB + lid*8 + 4];
            float z0 = la.x + ga.x, z1 = la.y + ga.y, z2 = la.z + ga.z;
            float z3 = la.w + ga.w, z4 = lb.x + gb.x, z5 = lb.y + gb.y;
            int best = 0; float bz = z0;
            if (z1 > bz) { bz = z1; best = 1; }
            if (z2 > bz) { bz = z2; best = 2; }
            if (z3 > bz) { bz = z3; best = 3; }
            if (z4 > bz) { bz = z4; best = 4; }
            if (z5 > bz) { bz = z5; best = 5; }
            float acc = S[OF_P + best*256 + t] + pre4;
            epi(acc, c0, &S[OF_H0A], l, rowIdx);
        }
        // ===== phase 4: call2-cell1 =====
        {
            float sa = dot64r(wi1, (const ulonglong2*)&S[OF_H0A]);
            float acc = b1R + (sa + sb1b);
            epi(acc, c1, &S[OF_H1A], l, rowIdx);
        }
        // ===== phase 5: anchor: w2out 4 thr/row over ALL warps + PA dot =====
        {
            int r = t >> 2, kk = t & 3;
            const float4* wv = (const float4*)&S[OF_WAT2 + r*PAD + kk*16];
            const float4* hv = (const float4*)&S[OF_H1A + kk*16];
            float4 wa = wv[0], wb = wv[1], wc = wv[2], wd = wv[3];
            float4 ha = hv[0], hb = hv[1], hc = hv[2], hd = hv[3];
            float s = wa.x*ha.x + wa.y*ha.y + wa.z*ha.z + wa.w*ha.w
                    + wb.x*hb.x + wb.y*hb.y + wb.z*hb.z + wb.w*hb.w
                    + wc.x*hc.x + wc.y*hc.y + wc.z*hc.z + wc.w*hc.w
                    + wd.x*hd.x + wd.y*hd.y + wd.z*hd.z + wd.w*hd.w;
            s += __shfl_down_sync(0xffffffffu, s, 2, 4);
            s += __shfl_down_sync(0xffffffffu, s, 1, 4);
            if (kk == 0) {
                S[OF_W2OUT + r] = s;
                S[OF_AW1 + lid*HID + r] = s;
            }
            float pa = dot64p((const ulonglong2*)&S[OF_WI0 + R*PAD],
                              (const ulonglong2*)&S[OF_H1A]);
            S[OF_PA + lid*256 + t] = pa;
            __syncthreads();
        }

        if (lid > 0) {
            // ===== phase 6: attention q + skip flags (16 thr/row) =====
            if (t < 192) {
                int r = t >> 4, k0 = t & 15;
                int rc = (r < lid) ? r : 0;
                float s = 0.f;
#pragma unroll
                for (int k = 0; k < 4; k++) {
                    int j = k0 + 16*k;
                    s += ftanh(S[OF_AW1 + rc*HID + j] + S[OF_W2OUT + j]) * S[OF_VATTN + j];
                }
                s += __shfl_down_sync(0xffffffffu, s, 8, 16);
                s += __shfl_down_sync(0xffffffffu, s, 4, 16);
                s += __shfl_down_sync(0xffffffffu, s, 2, 16);
                s += __shfl_down_sync(0xffffffffu, s, 1, 16);
                if (k0 == 0 && r < lid) {
                    S[OF_QVS + lid*16 + r] = s;
                    float l0 = 1.5f * ftanh(s);
                    float g0 = S[OF_GUMS + lid*(lid-1) + 2*r];
                    float g1 = S[OF_GUMS + lid*(lid-1) + 2*r + 1];
                    S[OF_SKF + r] = ((-l0) + g1 > l0 + g0) ? 1.0f : 0.0f;
                }
            }
            __syncthreads();
        }
    }

    // ===== deferred stats (once) =====
    if (t < 12) {
        float lv[NB];
#pragma unroll
        for (int j = 0; j < NB; j++) lv[j] = S[OF_LOGS + t*8 + j];
        float m = lv[0];
#pragma unroll
        for (int j = 1; j < NB; j++) m = fmaxf(m, lv[j]);
        float s = 0.f;
#pragma unroll
        for (int j = 0; j < NB; j++) s += __expf(lv[j] - m);
        float lse = __logf(s);
        int best = 0;
        float bz = lv[0] + S[OF_GUMB + t*8];
#pragma unroll
        for (int j = 1; j < NB; j++) {
            float z = lv[j] + S[OF_GUMB + t*8 + j];
            if (z > bz) { bz = z; best = j; }
        }
        S[OF_BLP + t] = (lv[best] - m) - lse;
        float ent = 0.f;
#pragma unroll
        for (int j = 0; j < NB; j++) {
            float lp = (lv[j] - m) - lse;
            ent -= __expf(lp) * lp;
        }
        S[OF_BENT + t] = ent;
    } else if (t >= 64 && t < 64 + 66) {
        int f = t - 64;
        int lid = 1;
        while (f >= (lid*(lid+1)) >> 1) lid++;
        int r = f - ((lid*(lid-1)) >> 1);
        float q = S[OF_QVS + lid*16 + r];
        float l0 = 1.5f * ftanh(q);
        float l1 = -l0;
        float g0 = S[OF_GUMS + lid*(lid-1) + 2*r];
        float g1 = S[OF_GUMS + lid*(lid-1) + 2*r + 1];
        float m = fmaxf(l0, l1);
        float lsr = __logf(__expf(l0 - m) + __expf(l1 - m));
        float lp0 = (l0 - m) - lsr;
        float lp1 = (l1 - m) - lsr;
        S[OF_SLP + f]  = (l1 + g1 > l0 + g0) ? lp1 : lp0;
        S[OF_SENT + f] = -(__expf(lp0)*lp0 + __expf(lp1)*lp1);
        float s0 = __fdividef(1.0f, 1.0f + __expf(-l0));
        float s1 = __fdividef(1.0f, 1.0f + __expf(-l1));
        S[OF_SKL + f] = s0 * __logf(__fdividef(s0, 0.8f))
                      + s1 * __logf(__fdividef(s1, 0.8f));
    }
    __syncthreads();

    if (t < 32) {
        float s1 = 0.f, s2 = 0.f, s3 = 0.f;
        for (int i = t; i < 12; i += 32) { s1 += S[OF_BLP + i]; s2 += S[OF_BENT + i]; }
        for (int i = t; i < 66; i += 32) {
            s1 += S[OF_SLP + i]; s2 += S[OF_SENT + i]; s3 += S[OF_SKL + i];
        }
#pragma unroll
        for (int off = 16; off > 0; off >>= 1) {
            s1 += __shfl_down_sync(0xffffffffu, s1, off);
            s2 += __shfl_down_sync(0xffffffffu, s2, off);
            s3 += __shfl_down_sync(0xffffffffu, s3, off);
        }
        if (t == 0) {
            out3[0] = s1;
            out3[1] = s2;
            out3[2] = s3;
        }
    }
}

extern "C" void kernel_launch(void* const* d_in, const int* in_sizes, int n_in,
                              void* d_out, int out_size) {
    const float* g_emb   = (const float*)d_in[0];
    const float* w_emb   = (const float*)d_in[1];
    const float* w_soft  = (const float*)d_in[2];
    const float* w_attn2 = (const float*)d_in[3];
    const float* v_attn  = (const float*)d_in[4];
    const float* w_ih0   = (const float*)d_in[5];
    const float* w_hh0   = (const float*)d_in[6];
    const float* b_ih0   = (const float*)d_in[7];
    const float* b_hh0   = (const float*)d_in[8];
    const float* w_ih1   = (const float*)d_in[9];
    const float* w_hh1   = (const float*)d_in[10];
    const float* b_ih1   = (const float*)d_in[11];
    const float* b_hh1   = (const float*)d_in[12];
    const int*   seed    = (const int*)d_in[13];

    cudaFuncSetAttribute(enas_controller_kernel,
                         cudaFuncAttributeMaxDynamicSharedMemorySize, SMEM_BYTES);
    enas_controller_kernel<<<1, 256, SMEM_BYTES>>>(
        g_emb, w_emb, w_soft, w_attn2, v_attn,
        w_ih0, w_hh0, b_ih0, b_hh0,
        w_ih1, w_hh1, b_ih1, b_hh1,
        seed, (float*)d_out);
}

// round 14
// speedup vs baseline: 1.0467x; 1.0467x over previous
#include <cuda_runtime.h>

// ============================================================================
// EnasController FINAL (== R9, empirical optimum at 55.3us, rel_err 0.0):
// - one persistent block, 256 threads, all state in smem/registers
// - wh0/wh1/wi1 rows register-resident; w_ih0/w_attn2 in padded smem
// - P table (precomputed cell0 inputs for all 6 branches + g_emb)
// - PA table rank reduction (skip-average folded into cell0 pre-activation;
//   xs phase deleted)
// - single-barrier LSTM cells (in-warp gate layout + shuffle epilogue,
//   c in registers, ping-pong h buffers)
// - fused logits + call2-cell0 phase; redundant per-thread argmax
// - all RNG (threefry key chain, 204 gumbels) hoisted before the loop
// - all softmax/entropy/KL stats deferred to one end-of-kernel pass
// 7 barrier phases per layer.
// ============================================================================

#define N_LAYERS 12
#define NB 6
#define HID 64
#define PAD 68

typedef unsigned long long u64;

// ---- shared memory layout (float offsets) ----
#define OF_WI0   0                        // 256*68
#define OF_WAT2  (OF_WI0 + 256*PAD)       // 64*68
#define OF_WSOFT (OF_WAT2 + 64*PAD)       // 384
#define OF_VATTN (OF_WSOFT + 384)         // 64
#define OF_WEMB  (OF_VATTN + 64)          // 384
#define OF_GEMB  (OF_WEMB + 384)          // 64
#define OF_P     (OF_GEMB + 64)           // 7*256  (t-indexed)
#define OF_PA    (OF_P + 7*256)           // 12*256 (t-indexed)
#define OF_H0A   (OF_PA + 12*256)
#define OF_H0B   (OF_H0A + 64)
#define OF_H1A   (OF_H0B + 64)
#define OF_H1B   (OF_H1A + 64)
#define OF_AW1   (OF_H1B + 64)            // 12*64
#define OF_W2OUT (OF_AW1 + 768)           // 64
#define OF_QVS   (OF_W2OUT + 64)          // 12*16
#define OF_LOGS  (OF_QVS + 192)           // 12*8
#define OF_GUMB  (OF_LOGS + 96)           // 12*8 (stride 8)
#define OF_GUMS  (OF_GUMB + 96)           // 136
#define OF_BLP   (OF_GUMS + 136)          // 12
#define OF_BENT  (OF_BLP + 12)            // 12
#define OF_SLP   (OF_BENT + 12)           // 68
#define OF_SENT  (OF_SLP + 68)            // 68
#define OF_SKL   (OF_SENT + 68)           // 68
#define OF_SKF   (OF_SKL + 68)            // 16
#define OF_IREG  (OF_SKF + 16)
#define SMEM_FLOATS (OF_IREG + 80)
#define SMEM_BYTES  (SMEM_FLOATS * 4)
#define IO_LKEY  0
#define IO_KB    24
#define IO_KS    48

#define FMA2(acc, w, x) \
    asm("fma.rn.f32x2 %0, %1, %2, %0;" : "+l"(acc) : "l"(w), "l"(x))

__device__ __forceinline__ float lo32(u64 v) { return __uint_as_float((unsigned)v); }
__device__ __forceinline__ float hi32(u64 v) { return __uint_as_float((unsigned)(v >> 32)); }

__device__ __forceinline__ unsigned rotl32(unsigned x, int r) {
    return (x << r) | (x >> (32 - r));
}

__device__ __forceinline__ void tf2x32(unsigned k0, unsigned k1,
                                       unsigned x0, unsigned x1,
                                       unsigned &o0, unsigned &o1) {
    const unsigned ks2 = k0 ^ k1 ^ 0x1BD11BDAu;
    x0 += k0; x1 += k1;
    x0+=x1; x1=rotl32(x1,13); x1^=x0;
    x0+=x1; x1=rotl32(x1,15); x1^=x0;
    x0+=x1; x1=rotl32(x1,26); x1^=x0;
    x0+=x1; x1=rotl32(x1, 6); x1^=x0;
    x0+=k1; x1+=ks2+1u;
    x0+=x1; x1=rotl32(x1,17); x1^=x0;
    x0+=x1; x1=rotl32(x1,29); x1^=x0;
    x0+=x1; x1=rotl32(x1,16); x1^=x0;
    x0+=x1; x1=rotl32(x1,24); x1^=x0;
    x0+=ks2; x1+=k0+2u;
    x0+=x1; x1=rotl32(x1,13); x1^=x0;
    x0+=x1; x1=rotl32(x1,15); x1^=x0;
    x0+=x1; x1=rotl32(x1,26); x1^=x0;
    x0+=x1; x1=rotl32(x1, 6); x1^=x0;
    x0+=k0; x1+=k1+3u;
    x0+=x1; x1=rotl32(x1,17); x1^=x0;
    x0+=x1; x1=rotl32(x1,29); x1^=x0;
    x0+=x1; x1=rotl32(x1,16); x1^=x0;
    x0+=x1; x1=rotl32(x1,24); x1^=x0;
    x0+=k1; x1+=ks2+4u;
    x0+=x1; x1=rotl32(x1,13); x1^=x0;
    x0+=x1; x1=rotl32(x1,15); x1^=x0;
    x0+=x1; x1=rotl32(x1,26); x1^=x0;
    x0+=x1; x1=rotl32(x1, 6); x1^=x0;
    x0+=ks2; x1+=k0+5u;
    o0 = x0; o1 = x1;
}

__device__ __forceinline__ unsigned rbits32(unsigned k0, unsigned k1, int idx) {
    unsigned o0, o1;
    tf2x32(k0, k1, 0u, (unsigned)idx, o0, o1);
    return o0 ^ o1;
}

__device__ __forceinline__ float gumbel_from_bits(unsigned bits) {
    const float TINY = 1.17549435e-38f;
    float f = __uint_as_float(0x3f800000u | (bits >> 9)) - 1.0f;
    float u = fmaxf(TINY, f + TINY);
    return -logf(-logf(u));
}

__device__ __forceinline__ float fsig(float x) {
    return __fdividef(1.0f, 1.0f + __expf(-x));
}
__device__ __forceinline__ float ftanh(float x) {
    float ax = fabsf(x);
    float e  = __expf(-2.0f * ax);
    float r  = __fdividef(1.0f - e, 1.0f + e);
    return copysignf(r, x);
}

__device__ __forceinline__ float dot64p(const ulonglong2* __restrict__ w,
                                        const ulonglong2* __restrict__ v) {
    u64 a0 = 0ull, a1 = 0ull, a2 = 0ull, a3 = 0ull;
#pragma unroll
    for (int k = 0; k < 16; k += 2) {
        ulonglong2 w0 = w[k], w1 = w[k + 1];
        ulonglong2 v0 = v[k], v1 = v[k + 1];
        FMA2(a0, w0.x, v0.x);
        FMA2(a1, w0.y, v0.y);
        FMA2(a2, w1.x, v1.x);
        FMA2(a3, w1.y, v1.y);
    }
    return ((lo32(a0) + hi32(a0)) + (lo32(a1) + hi32(a1)))
         + ((lo32(a2) + hi32(a2)) + (lo32(a3) + hi32(a3)));
}

__device__ __forceinline__ float dot64r(const u64* __restrict__ w,
                                        const ulonglong2* __restrict__ v) {
    u64 a0 = 0ull, a1 = 0ull, a2 = 0ull, a3 = 0ull;
#pragma unroll
    for (int k = 0; k < 16; k += 2) {
        ulonglong2 v0 = v[k], v1 = v[k + 1];
        FMA2(a0, w[2*k],     v0.x);
        FMA2(a1, w[2*k + 1], v0.y);
        FMA2(a2, w[2*k + 2], v1.x);
        FMA2(a3, w[2*k + 3], v1.y);
    }
    return ((lo32(a0) + hi32(a0)) + (lo32(a1) + hi32(a1)))
         + ((lo32(a2) + hi32(a2)) + (lo32(a3) + hi32(a3)));
}

// Epilogue: lane l holds pre-activation for gate (l>>3), row w*8+(l&7).
__device__ __forceinline__ void epi(float acc, float& c,
                                    float* __restrict__ hout,
                                    int l, int rowIdx) {
    int grp = l >> 3, r8 = l & 7;
    float act = (grp == 2) ? ftanh(acc) : fsig(acc);
    float ai = __shfl_sync(0xffffffffu, act, r8);
    float af = __shfl_sync(0xffffffffu, act, r8 + 8);
    float ag = __shfl_sync(0xffffffffu, act, r8 + 16);
    float ao = __shfl_sync(0xffffffffu, act, r8 + 24);
    float cn = af * c + ai * ag;
    c = cn;
    float hv = ao * ftanh(cn);
    if (l < 8) hout[rowIdx] = hv;
    __syncthreads();
}

__global__ __launch_bounds__(256, 1)
void enas_controller_kernel(const float* __restrict__ g_emb,
                            const float* __restrict__ w_emb,
                            const float* __restrict__ w_soft,
                            const float* __restrict__ w_attn2,
                            const float* __restrict__ v_attn,
                            const float* __restrict__ w_ih0,
                            const float* __restrict__ w_hh0,
                            const float* __restrict__ b_ih0,
                            const float* __restrict__ b_hh0,
                            const float* __restrict__ w_ih1,
                            const float* __restrict__ w_hh1,
                            const float* __restrict__ b_ih1,
                            const float* __restrict__ b_hh1,
                            const int* __restrict__ seed_p,
                            float* __restrict__ out3) {
    extern __shared__ __align__(16) float S[];
    unsigned* SI = (unsigned*)&S[OF_IREG];
    const int t = threadIdx.x;
    const int w = t >> 5, l = t & 31;
    const int grp = l >> 3, r8 = l & 7;
    const int rowIdx = w * 8 + r8;
    const int R = grp * 64 + rowIdx;

    // ---- stage weights into smem ----
    {
        const float4* g0 = (const float4*)w_ih0;
        for (int idx = t; idx < 256*16; idx += 256) {
            int row = idx >> 4, col = idx & 15;
            *(float4*)&S[OF_WI0 + row*PAD + col*4] = __ldg(&g0[idx]);
        }
        const float4* ga = (const float4*)w_attn2;
        for (int idx = t; idx < 64*16; idx += 256) {
            int row = idx >> 4, col = idx & 15;
            *(float4*)&S[OF_WAT2 + row*PAD + col*4] = __ldg(&ga[idx]);
        }
        const float4* gs = (const float4*)w_soft;
        if (t < NB*16) *(float4*)&S[OF_WSOFT + t*4] = __ldg(&gs[t]);
        const float4* ge = (const float4*)w_emb;
        if (t >= 32 && t < 32 + NB*16) *(float4*)&S[OF_WEMB + (t-32)*4] = __ldg(&ge[t-32]);
        if (t >= 128 && t < 144) *(float4*)&S[OF_GEMB + (t-128)*4] = __ldg(&((const float4*)g_emb)[t-128]);
        if (t >= 160 && t < 160 + HID) {
            S[OF_VATTN + t - 160] = __ldg(&v_attn[t - 160]);
            S[OF_H0A + t - 160] = 0.f;
            S[OF_H1A + t - 160] = 0.f;
        }
    }

    // ---- register weights: wh0, wh1, wi1 rows for gate row R ----
    u64 wh0[32], wh1[32], wi1[32];
    {
        const ulonglong2* p0 = (const ulonglong2*)(w_hh0 + R*HID);
        const ulonglong2* p1 = (const ulonglong2*)(w_hh1 + R*HID);
        const ulonglong2* p2 = (const ulonglong2*)(w_ih1 + R*HID);
#pragma unroll
        for (int k = 0; k < 16; k++) {
            ulonglong2 v0 = __ldg(&p0[k]);
            ulonglong2 v1 = __ldg(&p1[k]);
            ulonglong2 v2 = __ldg(&p2[k]);
            wh0[2*k] = v0.x; wh0[2*k + 1] = v0.y;
            wh1[2*k] = v1.x; wh1[2*k + 1] = v1.y;
            wi1[2*k] = v2.x; wi1[2*k + 1] = v2.y;
        }
    }
    const float b0R = __ldg(&b_ih0[R]) + __ldg(&b_hh0[R]);
    const float b1R = __ldg(&b_ih1[R]) + __ldg(&b_hh1[R]);

    // ---- RNG: serial key chain, then keys + all gumbels in parallel ----
    if (t == 0) {
        unsigned k0 = 0u, k1 = (unsigned)seed_p[0];
        for (int lid = 0; lid < N_LAYERS; lid++) {
            SI[IO_LKEY + 2*lid]     = k0;
            SI[IO_LKEY + 2*lid + 1] = k1;
            unsigned a0, a1;
            tf2x32(k0, k1, 0u, 0u, a0, a1);
            k0 = a0; k1 = a1;
        }
    }
    __syncthreads();
    if (t < 24) {
        int lid = t >> 1, which = t & 1;
        unsigned o0, o1;
        tf2x32(SI[IO_LKEY + 2*lid], SI[IO_LKEY + 2*lid + 1], 0u, (unsigned)(1 + which), o0, o1);
        int base = which ? IO_KS : IO_KB;
        SI[base + 2*lid] = o0; SI[base + 2*lid + 1] = o1;
    }
    // ---- P table (t-indexed): P[b][t] = b0R + wi0[R(t),:] . vec_b ----
    {
        const ulonglong2* wrow = (const ulonglong2*)&S[OF_WI0 + R*PAD];
#pragma unroll
        for (int b = 0; b < 7; b++) {
            const ulonglong2* vec = (const ulonglong2*)
                ((b < 6) ? &S[OF_WEMB + b*HID] : &S[OF_GEMB]);
            S[OF_P + b*256 + t] = b0R + dot64p(wrow, vec);
        }
    }
    __syncthreads();
    if (t < 72) {
        int lid = t / NB, j = t % NB;
        S[OF_GUMB + lid*8 + j] =
            gumbel_from_bits(rbits32(SI[IO_KB + 2*lid], SI[IO_KB + 2*lid + 1], j));
    } else if (t < 72 + 132) {
        int f = t - 72;
        int lid = 1;
        while (f >= lid*(lid+1)) lid++;
        int j = f - lid*(lid-1);
        S[OF_GUMS + f] =
            gumbel_from_bits(rbits32(SI[IO_KS + 2*lid], SI[IO_KS + 2*lid + 1], j));
    }
    __syncthreads();

    float c0 = 0.f, c1 = 0.f;

#pragma unroll 1
    for (int lid = 0; lid < N_LAYERS; ++lid) {
        // ===== phase 1: call1-cell0 (input via PA-sum for lid>=2) =====
        float sb1;
        {
            float acc;
            if (lid < 2) {
                acc = S[OF_P + 6*256 + t];
            } else {
                int nsk = lid - 1;
                float den = 1.0f, ps = 0.f;
                for (int i = 0; i < nsk; i++) {
                    float f = S[OF_SKF + i];
                    den += f;
                    ps = fmaf(f, S[OF_PA + i*256 + t], ps);
                }
                acc = b0R + __fdividef(ps, den);
            }
            acc += dot64r(wh0, (const ulonglong2*)&S[OF_H0A]);
            sb1 = dot64r(wh1, (const ulonglong2*)&S[OF_H1A]);
            epi(acc, c0, &S[OF_H0B], l, rowIdx);
        }
        // ===== phase 2: call1-cell1 =====
        {
            float sa = dot64r(wi1, (const ulonglong2*)&S[OF_H0B]);
            float acc = b1R + (sa + sb1);
            epi(acc, c1, &S[OF_H1B], l, rowIdx);
        }
        // ===== phase 3 (fused logits + call2-cell0) =====
        float sb1b;
        {
            if (t < 64) {
                int j = t >> 3, k0 = t & 7;
                int jc = (j < NB) ? j : 0;
                const float4* wv = (const float4*)&S[OF_WSOFT + jc*HID + k0*8];
                const float4* hv = (const float4*)&S[OF_H1B + k0*8];
                float4 wa = wv[0], wb = wv[1];
                float4 ha = hv[0], hb = hv[1];
                float s = wa.x*ha.x + wa.y*ha.y + wa.z*ha.z + wa.w*ha.w
                        + wb.x*hb.x + wb.y*hb.y + wb.z*hb.z + wb.w*hb.w;
                s += __shfl_down_sync(0xffffffffu, s, 4, 8);
                s += __shfl_down_sync(0xffffffffu, s, 2, 8);
                s += __shfl_down_sync(0xffffffffu, s, 1, 8);
                if (k0 == 0 && j < NB) S[OF_LOGS + lid*8 + j] = s;
            }
            float pre4 = dot64r(wh0, (const ulonglong2*)&S[OF_H0B]);
            sb1b = dot64r(wh1, (const ulonglong2*)&S[OF_H1B]);
            __syncthreads();

            float4 la = *(const float4*)&S[OF_LOGS + lid*8];
            float4 lb = *(const float4*)&S[OF_LOGS + lid*8 + 4];
            float4 ga = *(const float4*)&S[OF_GUMB + lid*8];
            float4 gb = *(const float4*)&S[OF_GUMB + lid*8 + 4];
            float z0 = la.x + ga.x, z1 = la.y + ga.y, z2 = la.z + ga.z;
            float z3 = la.w + ga.w, z4 = lb.x + gb.x, z5 = lb.y + gb.y;
            int best = 0; float bz = z0;
            if (z1 > bz) { bz = z1; best = 1; }
            if (z2 > bz) { bz = z2; best = 2; }
            if (z3 > bz) { bz = z3; best = 3; }
            if (z4 > bz) { bz = z4; best = 4; }
            if (z5 > bz) { bz = z5; best = 5; }
            float acc = S[OF_P + best*256 + t] + pre4;
            epi(acc, c0, &S[OF_H0A], l, rowIdx);
        }
        // ===== phase 4: call2-cell1 =====
        {
            float sa = dot64r(wi1, (const ulonglong2*)&S[OF_H0A]);
            float acc = b1R + (sa + sb1b);
            epi(acc, c1, &S[OF_H1A], l, rowIdx);
        }
        // ===== phase 5: anchor: warps 6-7 w2out/AW1; all threads PA =====
        {
            if (t >= 192) {
                int r = t - 192;
                float v = dot64p((const ulonglong2*)&S[OF_WAT2 + r*PAD],
                                 (const ulonglong2*)&S[OF_H1A]);
                S[OF_W2OUT + r] = v;
                S[OF_AW1 + lid*HID + r] = v;
            }
            float pa = dot64p((const ulonglong2*)&S[OF_WI0 + R*PAD],
                              (const ulonglong2*)&S[OF_H1A]);
            S[OF_PA + lid*256 + t] = pa;
            __syncthreads();
        }

        if (lid > 0) {
            // ===== phase 6: attention q + skip flags (16 thr/row) =====
            if (t < 192) {
                int r = t >> 4, k0 = t & 15;
                int rc = (r < lid) ? r : 0;
                float s = 0.f;
#pragma unroll
                for (int k = 0; k < 4; k++) {
                    int j = k0 + 16*k;
                    s += ftanh(S[OF_AW1 + rc*HID + j] + S[OF_W2OUT + j]) * S[OF_VATTN + j];
                }
                s += __shfl_down_sync(0xffffffffu, s, 8, 16);
                s += __shfl_down_sync(0xffffffffu, s, 4, 16);
                s += __shfl_down_sync(0xffffffffu, s, 2, 16);
                s += __shfl_down_sync(0xffffffffu, s, 1, 16);
                if (k0 == 0 && r < lid) {
                    S[OF_QVS + lid*16 + r] = s;
                    float l0 = 1.5f * ftanh(s);
                    float g0 = S[OF_GUMS + lid*(lid-1) + 2*r];
                    float g1 = S[OF_GUMS + lid*(lid-1) + 2*r + 1];
                    S[OF_SKF + r] = ((-l0) + g1 > l0 + g0) ? 1.0f : 0.0f;
                }
            }
            __syncthreads();
        }
    }

    // ===== deferred stats (once) =====
    if (t < 12) {
        float lv[NB];
#pragma unroll
        for (int j = 0; j < NB; j++) lv[j] = S[OF_LOGS + t*8 + j];
        float m = lv[0];
#pragma unroll
        for (int j = 1; j < NB; j++) m = fmaxf(m, lv[j]);
        float s = 0.f;
#pragma unroll
        for (int j = 0; j < NB; j++) s += __expf(lv[j] - m);
        float lse = __logf(s);
        int best = 0;
        float bz = lv[0] + S[OF_GUMB + t*8];
#pragma unroll
        for (int j = 1; j < NB; j++) {
            float z = lv[j] + S[OF_GUMB + t*8 + j];
            if (z > bz) { bz = z; best = j; }
        }
        S[OF_BLP + t] = (lv[best] - m) - lse;
        float ent = 0.f;
#pragma unroll
        for (int j = 0; j < NB; j++) {
            float lp = (lv[j] - m) - lse;
            ent -= __expf(lp) * lp;
        }
        S[OF_BENT + t] = ent;
    } else if (t >= 64 && t < 64 + 66) {
        int f = t - 64;
        int lid = 1;
        while (f >= (lid*(lid+1)) >> 1) lid++;
        int r = f - ((lid*(lid-1)) >> 1);
        float q = S[OF_QVS + lid*16 + r];
        float l0 = 1.5f * ftanh(q);
        float l1 = -l0;
        float g0 = S[OF_GUMS + lid*(lid-1) + 2*r];
        float g1 = S[OF_GUMS + lid*(lid-1) + 2*r + 1];
        float m = fmaxf(l0, l1);
        float lsr = __logf(__expf(l0 - m) + __expf(l1 - m));
        float lp0 = (l0 - m) - lsr;
        float lp1 = (l1 - m) - lsr;
        S[OF_SLP + f]  = (l1 + g1 > l0 + g0) ? lp1 : lp0;
        S[OF_SENT + f] = -(__expf(lp0)*lp0 + __expf(lp1)*lp1);
        float s0 = __fdividef(1.0f, 1.0f + __expf(-l0));
        float s1 = __fdividef(1.0f, 1.0f + __expf(-l1));
        S[OF_SKL + f] = s0 * __logf(__fdividef(s0, 0.8f))
                      + s1 * __logf(__fdividef(s1, 0.8f));
    }
    __syncthreads();

    if (t < 32) {
        float s1 = 0.f, s2 = 0.f, s3 = 0.f;
        for (int i = t; i < 12; i += 32) { s1 += S[OF_BLP + i]; s2 += S[OF_BENT + i]; }
        for (int i = t; i < 66; i += 32) {
            s1 += S[OF_SLP + i]; s2 += S[OF_SENT + i]; s3 += S[OF_SKL + i];
        }
#pragma unroll
        for (int off = 16; off > 0; off >>= 1) {
            s1 += __shfl_down_sync(0xffffffffu, s1, off);
            s2 += __shfl_down_sync(0xffffffffu, s2, off);
            s3 += __shfl_down_sync(0xffffffffu, s3, off);
        }
        if (t == 0) {
            out3[0] = s1;
            out3[1] = s2;
            out3[2] = s3;
        }
    }
}

extern "C" void kernel_launch(void* const* d_in, const int* in_sizes, int n_in,
                              void* d_out, int out_size) {
    const float* g_emb   = (const float*)d_in[0];
    const float* w_emb   = (const float*)d_in[1];
    const float* w_soft  = (const float*)d_in[2];
    const float* w_attn2 = (const float*)d_in[3];
    const float* v_attn  = (const float*)d_in[4];
    const float* w_ih0   = (const float*)d_in[5];
    const float* w_hh0   = (const float*)d_in[6];
    const float* b_ih0   = (const float*)d_in[7];
    const float* b_hh0   = (const float*)d_in[8];
    const float* w_ih1   = (const float*)d_in[9];
    const float* w_hh1   = (const float*)d_in[10];
    const float* b_ih1   = (const float*)d_in[11];
    const float* b_hh1   = (const float*)d_in[12];
    const int*   seed    = (const int*)d_in[13];

    cudaFuncSetAttribute(enas_controller_kernel,
                         cudaFuncAttributeMaxDynamicSharedMemorySize, SMEM_BYTES);
    enas_controller_kernel<<<1, 256, SMEM_BYTES>>>(
        g_emb, w_emb, w_soft, w_attn2, v_attn,
        w_ih0, w_hh0, b_ih0, b_hh0,
        w_ih1, w_hh1, b_ih1, b_hh1,
        seed, (float*)d_out);
}

// round 15
// speedup vs baseline: 1.2166x; 1.1623x over previous
#include <cuda_runtime.h>

// ============================================================================
// EnasController R15: R9 structure (confirmed optimum, 54.8us) with MUFU.TANH
// (tanh.approx.f32) replacing the exp-based activations in the convoy-critical
// cell epilogues and attention chain. Free-option experiment: shortens the
// longest serial chains by ~4-5K cycles; small risk of a sample flip.
// ============================================================================

#define N_LAYERS 12
#define NB 6
#define HID 64
#define PAD 68

typedef unsigned long long u64;

// ---- shared memory layout (float offsets) ----
#define OF_WI0   0                        // 256*68
#define OF_WAT2  (OF_WI0 + 256*PAD)       // 64*68
#define OF_WSOFT (OF_WAT2 + 64*PAD)       // 384
#define OF_VATTN (OF_WSOFT + 384)         // 64
#define OF_WEMB  (OF_VATTN + 64)          // 384
#define OF_GEMB  (OF_WEMB + 384)          // 64
#define OF_P     (OF_GEMB + 64)           // 7*256  (t-indexed)
#define OF_PA    (OF_P + 7*256)           // 12*256 (t-indexed)
#define OF_H0A   (OF_PA + 12*256)
#define OF_H0B   (OF_H0A + 64)
#define OF_H1A   (OF_H0B + 64)
#define OF_H1B   (OF_H1A + 64)
#define OF_AW1   (OF_H1B + 64)            // 12*64
#define OF_W2OUT (OF_AW1 + 768)           // 64
#define OF_QVS   (OF_W2OUT + 64)          // 12*16
#define OF_LOGS  (OF_QVS + 192)           // 12*8
#define OF_GUMB  (OF_LOGS + 96)           // 12*8 (stride 8)
#define OF_GUMS  (OF_GUMB + 96)           // 136
#define OF_BLP   (OF_GUMS + 136)          // 12
#define OF_BENT  (OF_BLP + 12)            // 12
#define OF_SLP   (OF_BENT + 12)           // 68
#define OF_SENT  (OF_SLP + 68)            // 68
#define OF_SKL   (OF_SENT + 68)           // 68
#define OF_SKF   (OF_SKL + 68)            // 16
#define OF_IREG  (OF_SKF + 16)
#define SMEM_FLOATS (OF_IREG + 80)
#define SMEM_BYTES  (SMEM_FLOATS * 4)
#define IO_LKEY  0
#define IO_KB    24
#define IO_KS    48

#define FMA2(acc, w, x) \
    asm("fma.rn.f32x2 %0, %1, %2, %0;" : "+l"(acc) : "l"(w), "l"(x))

__device__ __forceinline__ float lo32(u64 v) { return __uint_as_float((unsigned)v); }
__device__ __forceinline__ float hi32(u64 v) { return __uint_as_float((unsigned)(v >> 32)); }

__device__ __forceinline__ unsigned rotl32(unsigned x, int r) {
    return (x << r) | (x >> (32 - r));
}

__device__ __forceinline__ void tf2x32(unsigned k0, unsigned k1,
                                       unsigned x0, unsigned x1,
                                       unsigned &o0, unsigned &o1) {
    const unsigned ks2 = k0 ^ k1 ^ 0x1BD11BDAu;
    x0 += k0; x1 += k1;
    x0+=x1; x1=rotl32(x1,13); x1^=x0;
    x0+=x1; x1=rotl32(x1,15); x1^=x0;
    x0+=x1; x1=rotl32(x1,26); x1^=x0;
    x0+=x1; x1=rotl32(x1, 6); x1^=x0;
    x0+=k1; x1+=ks2+1u;
    x0+=x1; x1=rotl32(x1,17); x1^=x0;
    x0+=x1; x1=rotl32(x1,29); x1^=x0;
    x0+=x1; x1=rotl32(x1,16); x1^=x0;
    x0+=x1; x1=rotl32(x1,24); x1^=x0;
    x0+=ks2; x1+=k0+2u;
    x0+=x1; x1=rotl32(x1,13); x1^=x0;
    x0+=x1; x1=rotl32(x1,15); x1^=x0;
    x0+=x1; x1=rotl32(x1,26); x1^=x0;
    x0+=x1; x1=rotl32(x1, 6); x1^=x0;
    x0+=k0; x1+=k1+3u;
    x0+=x1; x1=rotl32(x1,17); x1^=x0;
    x0+=x1; x1=rotl32(x1,29); x1^=x0;
    x0+=x1; x1=rotl32(x1,16); x1^=x0;
    x0+=x1; x1=rotl32(x1,24); x1^=x0;
    x0+=k1; x1+=ks2+4u;
    x0+=x1; x1=rotl32(x1,13); x1^=x0;
    x0+=x1; x1=rotl32(x1,15); x1^=x0;
    x0+=x1; x1=rotl32(x1,26); x1^=x0;
    x0+=x1; x1=rotl32(x1, 6); x1^=x0;
    x0+=ks2; x1+=k0+5u;
    o0 = x0; o1 = x1;
}

__device__ __forceinline__ unsigned rbits32(unsigned k0, unsigned k1, int idx) {
    unsigned o0, o1;
    tf2x32(k0, k1, 0u, (unsigned)idx, o0, o1);
    return o0 ^ o1;
}

__device__ __forceinline__ float gumbel_from_bits(unsigned bits) {
    const float TINY = 1.17549435e-38f;
    float f = __uint_as_float(0x3f800000u | (bits >> 9)) - 1.0f;
    float u = fmaxf(TINY, f + TINY);
    return -logf(-logf(u));
}

// HW tanh (MUFU.TANH) and sigmoid via tanh identity — used in the hot loop
__device__ __forceinline__ float tapx(float x) {
    float y;
    asm("tanh.approx.f32 %0, %1;" : "=f"(y) : "f"(x));
    return y;
}
__device__ __forceinline__ float sapx(float x) {
    return fmaf(tapx(0.5f * x), 0.5f, 0.5f);
}

__device__ __forceinline__ float dot64p(const ulonglong2* __restrict__ w,
                                        const ulonglong2* __restrict__ v) {
    u64 a0 = 0ull, a1 = 0ull, a2 = 0ull, a3 = 0ull;
#pragma unroll
    for (int k = 0; k < 16; k += 2) {
        ulonglong2 w0 = w[k], w1 = w[k + 1];
        ulonglong2 v0 = v[k], v1 = v[k + 1];
        FMA2(a0, w0.x, v0.x);
        FMA2(a1, w0.y, v0.y);
        FMA2(a2, w1.x, v1.x);
        FMA2(a3, w1.y, v1.y);
    }
    return ((lo32(a0) + hi32(a0)) + (lo32(a1) + hi32(a1)))
         + ((lo32(a2) + hi32(a2)) + (lo32(a3) + hi32(a3)));
}

__device__ __forceinline__ float dot64r(const u64* __restrict__ w,
                                        const ulonglong2* __restrict__ v) {
    u64 a0 = 0ull, a1 = 0ull, a2 = 0ull, a3 = 0ull;
#pragma unroll
    for (int k = 0; k < 16; k += 2) {
        ulonglong2 v0 = v[k], v1 = v[k + 1];
        FMA2(a0, w[2*k],     v0.x);
        FMA2(a1, w[2*k + 1], v0.y);
        FMA2(a2, w[2*k + 2], v1.x);
        FMA2(a3, w[2*k + 3], v1.y);
    }
    return ((lo32(a0) + hi32(a0)) + (lo32(a1) + hi32(a1)))
         + ((lo32(a2) + hi32(a2)) + (lo32(a3) + hi32(a3)));
}

// Epilogue: lane l holds pre-activation for gate (l>>3), row w*8+(l&7).
// MUFU.TANH activations (short chain).
__device__ __forceinline__ void epi(float acc, float& c,
                                    float* __restrict__ hout,
                                    int l, int rowIdx) {
    int grp = l >> 3, r8 = l & 7;
    float act = (grp == 2) ? tapx(acc) : sapx(acc);
    float ai = __shfl_sync(0xffffffffu, act, r8);
    float af = __shfl_sync(0xffffffffu, act, r8 + 8);
    float ag = __shfl_sync(0xffffffffu, act, r8 + 16);
    float ao = __shfl_sync(0xffffffffu, act, r8 + 24);
    float cn = af * c + ai * ag;
    c = cn;
    float hv = ao * tapx(cn);
    if (l < 8) hout[rowIdx] = hv;
    __syncthreads();
}

__global__ __launch_bounds__(256, 1)
void enas_controller_kernel(const float* __restrict__ g_emb,
                            const float* __restrict__ w_emb,
                            const float* __restrict__ w_soft,
                            const float* __restrict__ w_attn2,
                            const float* __restrict__ v_attn,
                            const float* __restrict__ w_ih0,
                            const float* __restrict__ w_hh0,
                            const float* __restrict__ b_ih0,
                            const float* __restrict__ b_hh0,
                            const float* __restrict__ w_ih1,
                            const float* __restrict__ w_hh1,
                            const float* __restrict__ b_ih1,
                            const float* __restrict__ b_hh1,
                            const int* __restrict__ seed_p,
                            float* __restrict__ out3) {
    extern __shared__ __align__(16) float S[];
    unsigned* SI = (unsigned*)&S[OF_IREG];
    const int t = threadIdx.x;
    const int w = t >> 5, l = t & 31;
    const int grp = l >> 3, r8 = l & 7;
    const int rowIdx = w * 8 + r8;
    const int R = grp * 64 + rowIdx;

    // ---- stage weights into smem ----
    {
        const float4* g0 = (const float4*)w_ih0;
        for (int idx = t; idx < 256*16; idx += 256) {
            int row = idx >> 4, col = idx & 15;
            *(float4*)&S[OF_WI0 + row*PAD + col*4] = __ldg(&g0[idx]);
        }
        const float4* ga = (const float4*)w_attn2;
        for (int idx = t; idx < 64*16; idx += 256) {
            int row = idx >> 4, col = idx & 15;
            *(float4*)&S[OF_WAT2 + row*PAD + col*4] = __ldg(&ga[idx]);
        }
        const float4* gs = (const float4*)w_soft;
        if (t < NB*16) *(float4*)&S[OF_WSOFT + t*4] = __ldg(&gs[t]);
        const float4* ge = (const float4*)w_emb;
        if (t >= 32 && t < 32 + NB*16) *(float4*)&S[OF_WEMB + (t-32)*4] = __ldg(&ge[t-32]);
        if (t >= 128 && t < 144) *(float4*)&S[OF_GEMB + (t-128)*4] = __ldg(&((const float4*)g_emb)[t-128]);
        if (t >= 160 && t < 160 + HID) {
            S[OF_VATTN + t - 160] = __ldg(&v_attn[t - 160]);
            S[OF_H0A + t - 160] = 0.f;
            S[OF_H1A + t - 160] = 0.f;
        }
    }

    // ---- register weights: wh0, wh1, wi1 rows for gate row R ----
    u64 wh0[32], wh1[32], wi1[32];
    {
        const ulonglong2* p0 = (const ulonglong2*)(w_hh0 + R*HID);
        const ulonglong2* p1 = (const ulonglong2*)(w_hh1 + R*HID);
        const ulonglong2* p2 = (const ulonglong2*)(w_ih1 + R*HID);
#pragma unroll
        for (int k = 0; k < 16; k++) {
            ulonglong2 v0 = __ldg(&p0[k]);
            ulonglong2 v1 = __ldg(&p1[k]);
            ulonglong2 v2 = __ldg(&p2[k]);
            wh0[2*k] = v0.x; wh0[2*k + 1] = v0.y;
            wh1[2*k] = v1.x; wh1[2*k + 1] = v1.y;
            wi1[2*k] = v2.x; wi1[2*k + 1] = v2.y;
        }
    }
    const float b0R = __ldg(&b_ih0[R]) + __ldg(&b_hh0[R]);
    const float b1R = __ldg(&b_ih1[R]) + __ldg(&b_hh1[R]);

    // ---- RNG: serial key chain, then keys + all gumbels in parallel ----
    if (t == 0) {
        unsigned k0 = 0u, k1 = (unsigned)seed_p[0];
        for (int lid = 0; lid < N_LAYERS; lid++) {
            SI[IO_LKEY + 2*lid]     = k0;
            SI[IO_LKEY + 2*lid + 1] = k1;
            unsigned a0, a1;
            tf2x32(k0, k1, 0u, 0u, a0, a1);
            k0 = a0; k1 = a1;
        }
    }
    __syncthreads();
    if (t < 24) {
        int lid = t >> 1, which = t & 1;
        unsigned o0, o1;
        tf2x32(SI[IO_LKEY + 2*lid], SI[IO_LKEY + 2*lid + 1], 0u, (unsigned)(1 + which), o0, o1);
        int base = which ? IO_KS : IO_KB;
        SI[base + 2*lid] = o0; SI[base + 2*lid + 1] = o1;
    }
    // ---- P table (t-indexed): P[b][t] = b0R + wi0[R(t),:] . vec_b ----
    {
        const ulonglong2* wrow = (const ulonglong2*)&S[OF_WI0 + R*PAD];
#pragma unroll
        for (int b = 0; b < 7; b++) {
            const ulonglong2* vec = (const ulonglong2*)
                ((b < 6) ? &S[OF_WEMB + b*HID] : &S[OF_GEMB]);
            S[OF_P + b*256 + t] = b0R + dot64p(wrow, vec);
        }
    }
    __syncthreads();
    if (t < 72) {
        int lid = t / NB, j = t % NB;
        S[OF_GUMB + lid*8 + j] =
            gumbel_from_bits(rbits32(SI[IO_KB + 2*lid], SI[IO_KB + 2*lid + 1], j));
    } else if (t < 72 + 132) {
        int f = t - 72;
        int lid = 1;
        while (f >= lid*(lid+1)) lid++;
        int j = f - lid*(lid-1);
        S[OF_GUMS + f] =
            gumbel_from_bits(rbits32(SI[IO_KS + 2*lid], SI[IO_KS + 2*lid + 1], j));
    }
    __syncthreads();

    float c0 = 0.f, c1 = 0.f;

#pragma unroll 1
    for (int lid = 0; lid < N_LAYERS; ++lid) {
        // ===== phase 1: call1-cell0 (input via PA-sum for lid>=2) =====
        float sb1;
        {
            float acc;
            if (lid < 2) {
                acc = S[OF_P + 6*256 + t];
            } else {
                int nsk = lid - 1;
                float den = 1.0f, ps = 0.f;
                for (int i = 0; i < nsk; i++) {
                    float f = S[OF_SKF + i];
                    den += f;
                    ps = fmaf(f, S[OF_PA + i*256 + t], ps);
                }
                acc = b0R + __fdividef(ps, den);
            }
            acc += dot64r(wh0, (const ulonglong2*)&S[OF_H0A]);
            sb1 = dot64r(wh1, (const ulonglong2*)&S[OF_H1A]);
            epi(acc, c0, &S[OF_H0B], l, rowIdx);
        }
        // ===== phase 2: call1-cell1 =====
        {
            float sa = dot64r(wi1, (const ulonglong2*)&S[OF_H0B]);
            float acc = b1R + (sa + sb1);
            epi(acc, c1, &S[OF_H1B], l, rowIdx);
        }
        // ===== phase 3 (fused logits + call2-cell0) =====
        float sb1b;
        {
            if (t < 64) {
                int j = t >> 3, k0 = t & 7;
                int jc = (j < NB) ? j : 0;
                const float4* wv = (const float4*)&S[OF_WSOFT + jc*HID + k0*8];
                const float4* hv = (const float4*)&S[OF_H1B + k0*8];
                float4 wa = wv[0], wb = wv[1];
                float4 ha = hv[0], hb = hv[1];
                float s = wa.x*ha.x + wa.y*ha.y + wa.z*ha.z + wa.w*ha.w
                        + wb.x*hb.x + wb.y*hb.y + wb.z*hb.z + wb.w*hb.w;
                s += __shfl_down_sync(0xffffffffu, s, 4, 8);
                s += __shfl_down_sync(0xffffffffu, s, 2, 8);
                s += __shfl_down_sync(0xffffffffu, s, 1, 8);
                if (k0 == 0 && j < NB) S[OF_LOGS + lid*8 + j] = s;
            }
            float pre4 = dot64r(wh0, (const ulonglong2*)&S[OF_H0B]);
            sb1b = dot64r(wh1, (const ulonglong2*)&S[OF_H1B]);
            __syncthreads();

            float4 la = *(const float4*)&S[OF_LOGS + lid*8];
            float4 lb = *(const float4*)&S[OF_LOGS + lid*8 + 4];
            float4 ga = *(const float4*)&S[OF_GUMB + lid*8];
            float4 gb = *(const float4*)&S[OF_GUMB + lid*8 + 4];
            float z0 = la.x + ga.x, z1 = la.y + ga.y, z2 = la.z + ga.z;
            float z3 = la.w + ga.w, z4 = lb.x + gb.x, z5 = lb.y + gb.y;
            int best = 0; float bz = z0;
            if (z1 > bz) { bz = z1; best = 1; }
            if (z2 > bz) { bz = z2; best = 2; }
            if (z3 > bz) { bz = z3; best = 3; }
            if (z4 > bz) { bz = z4; best = 4; }
            if (z5 > bz) { bz = z5; best = 5; }
            float acc = S[OF_P + best*256 + t] + pre4;
            epi(acc, c0, &S[OF_H0A], l, rowIdx);
        }
        // ===== phase 4: call2-cell1 =====
        {
            float sa = dot64r(wi1, (const ulonglong2*)&S[OF_H0A]);
            float acc = b1R + (sa + sb1b);
            epi(acc, c1, &S[OF_H1A], l, rowIdx);
        }
        // ===== phase 5: anchor: warps 6-7 w2out/AW1; all threads PA =====
        {
            if (t >= 192) {
                int r = t - 192;
                float v = dot64p((const ulonglong2*)&S[OF_WAT2 + r*PAD],
                                 (const ulonglong2*)&S[OF_H1A]);
                S[OF_W2OUT + r] = v;
                S[OF_AW1 + lid*HID + r] = v;
            }
            float pa = dot64p((const ulonglong2*)&S[OF_WI0 + R*PAD],
                              (const ulonglong2*)&S[OF_H1A]);
            S[OF_PA + lid*256 + t] = pa;
            __syncthreads();
        }

        if (lid > 0) {
            // ===== phase 6: attention q + skip flags (16 thr/row; MUFU tanh) =====
            if (t < 192) {
                int r = t >> 4, k0 = t & 15;
                int rc = (r < lid) ? r : 0;
                float s = 0.f;
#pragma unroll
                for (int k = 0; k < 4; k++) {
                    int j = k0 + 16*k;
                    s += tapx(S[OF_AW1 + rc*HID + j] + S[OF_W2OUT + j]) * S[OF_VATTN + j];
                }
                s += __shfl_down_sync(0xffffffffu, s, 8, 16);
                s += __shfl_down_sync(0xffffffffu, s, 4, 16);
                s += __shfl_down_sync(0xffffffffu, s, 2, 16);
                s += __shfl_down_sync(0xffffffffu, s, 1, 16);
                if (k0 == 0 && r < lid) {
                    S[OF_QVS + lid*16 + r] = s;
                    float l0 = 1.5f * tapx(s);
                    float g0 = S[OF_GUMS + lid*(lid-1) + 2*r];
                    float g1 = S[OF_GUMS + lid*(lid-1) + 2*r + 1];
                    S[OF_SKF + r] = ((-l0) + g1 > l0 + g0) ? 1.0f : 0.0f;
                }
            }
            __syncthreads();
        }
    }

    // ===== deferred stats (once) =====
    if (t < 12) {
        float lv[NB];
#pragma unroll
        for (int j = 0; j < NB; j++) lv[j] = S[OF_LOGS + t*8 + j];
        float m = lv[0];
#pragma unroll
        for (int j = 1; j < NB; j++) m = fmaxf(m, lv[j]);
        float s = 0.f;
#pragma unroll
        for (int j = 0; j < NB; j++) s += __expf(lv[j] - m);
        float lse = __logf(s);
        int best = 0;
        float bz = lv[0] + S[OF_GUMB + t*8];
#pragma unroll
        for (int j = 1; j < NB; j++) {
            float z = lv[j] + S[OF_GUMB + t*8 + j];
            if (z > bz) { bz = z; best = j; }
        }
        S[OF_BLP + t] = (lv[best] - m) - lse;
        float ent = 0.f;
#pragma unroll
        for (int j = 0; j < NB; j++) {
            float lp = (lv[j] - m) - lse;
            ent -= __expf(lp) * lp;
        }
        S[OF_BENT + t] = ent;
    } else if (t >= 64 && t < 64 + 66) {
        int f = t - 64;
        int lid = 1;
        while (f >= (lid*(lid+1)) >> 1) lid++;
        int r = f - ((lid*(lid-1)) >> 1);
        float q = S[OF_QVS + lid*16 + r];
        float l0 = 1.5f * tapx(q);         // identical op to the in-loop decision
        float l1 = -l0;
        float g0 = S[OF_GUMS + lid*(lid-1) + 2*r];
        float g1 = S[OF_GUMS + lid*(lid-1) + 2*r + 1];
        float m = fmaxf(l0, l1);
        float lsr = __logf(__expf(l0 - m) + __expf(l1 - m));
        float lp0 = (l0 - m) - lsr;
        float lp1 = (l1 - m) - lsr;
        S[OF_SLP + f]  = (l1 + g1 > l0 + g0) ? lp1 : lp0;
        S[OF_SENT + f] = -(__expf(lp0)*lp0 + __expf(lp1)*lp1);
        float s0 = __fdividef(1.0f, 1.0f + __expf(-l0));
        float s1 = __fdividef(1.0f, 1.0f + __expf(-l1));
        S[OF_SKL + f] = s0 * __logf(__fdividef(s0, 0.8f))
                      + s1 * __logf(__fdividef(s1, 0.8f));
    }
    __syncthreads();

    if (t < 32) {
        float s1 = 0.f, s2 = 0.f, s3 = 0.f;
        for (int i = t; i < 12; i += 32) { s1 += S[OF_BLP + i]; s2 += S[OF_BENT + i]; }
        for (int i = t; i < 66; i += 32) {
            s1 += S[OF_SLP + i]; s2 += S[OF_SENT + i]; s3 += S[OF_SKL + i];
        }
#pragma unroll
        for (int off = 16; off > 0; off >>= 1) {
            s1 += __shfl_down_sync(0xffffffffu, s1, off);
            s2 += __shfl_down_sync(0xffffffffu, s2, off);
            s3 += __shfl_down_sync(0xffffffffu, s3, off);
        }
        if (t == 0) {
            out3[0] = s1;
            out3[1] = s2;
            out3[2] = s3;
        }
    }
}

extern "C" void kernel_launch(void* const* d_in, const int* in_sizes, int n_in,
                              void* d_out, int out_size) {
    const float* g_emb   = (const float*)d_in[0];
    const float* w_emb   = (const float*)d_in[1];
    const float* w_soft  = (const float*)d_in[2];
    const float* w_attn2 = (const float*)d_in[3];
    const float* v_attn  = (const float*)d_in[4];
    const float* w_ih0   = (const float*)d_in[5];
    const float* w_hh0   = (const float*)d_in[6];
    const float* b_ih0   = (const float*)d_in[7];
    const float* b_hh0   = (const float*)d_in[8];
    const float* w_ih1   = (const float*)d_in[9];
    const float* w_hh1   = (const float*)d_in[10];
    const float* b_ih1   = (const float*)d_in[11];
    const float* b_hh1   = (const float*)d_in[12];
    const int*   seed    = (const int*)d_in[13];

    cudaFuncSetAttribute(enas_controller_kernel,
                         cudaFuncAttributeMaxDynamicSharedMemorySize, SMEM_BYTES);
    enas_controller_kernel<<<1, 256, SMEM_BYTES>>>(
        g_emb, w_emb, w_soft, w_attn2, v_attn,
        w_ih0, w_hh0, b_ih0, b_hh0,
        w_ih1, w_hh1, b_ih1, b_hh1,
        seed, (float*)d_out);
}

// round 16
// speedup vs baseline: 1.2182x; 1.0014x over previous
#include <cuda_runtime.h>

// ============================================================================
// EnasController R16: R15 (MUFU.TANH, 47.1us) + convoy leveling via bitwise-
// safe dot hoisting: pre4 -> ph2, next-layer wh0 dot -> ph4, next-layer wh1
// dot -> ph5 (sharing H1A vector loads with the PA dot). ph1 has NO dots.
// 256 threads; wh0/wh1/wi1 register-resident; PA rank reduction; deferred stats.
// ============================================================================

#define N_LAYERS 12
#define NB 6
#define HID 64
#define PAD 68

typedef unsigned long long u64;

// ---- shared memory layout (float offsets) ----
#define OF_WI0   0                        // 256*68
#define OF_WAT2  (OF_WI0 + 256*PAD)       // 64*68
#define OF_WSOFT (OF_WAT2 + 64*PAD)       // 384
#define OF_VATTN (OF_WSOFT + 384)         // 64
#define OF_WEMB  (OF_VATTN + 64)          // 384
#define OF_GEMB  (OF_WEMB + 384)          // 64
#define OF_P     (OF_GEMB + 64)           // 7*256  (t-indexed)
#define OF_PA    (OF_P + 7*256)           // 12*256 (t-indexed)
#define OF_H0A   (OF_PA + 12*256)
#define OF_H0B   (OF_H0A + 64)
#define OF_H1A   (OF_H0B + 64)
#define OF_H1B   (OF_H1A + 64)
#define OF_AW1   (OF_H1B + 64)            // 12*64
#define OF_W2OUT (OF_AW1 + 768)           // 64
#define OF_QVS   (OF_W2OUT + 64)          // 12*16
#define OF_LOGS  (OF_QVS + 192)           // 12*8
#define OF_GUMB  (OF_LOGS + 96)           // 12*8 (stride 8)
#define OF_GUMS  (OF_GUMB + 96)           // 136
#define OF_BLP   (OF_GUMS + 136)          // 12
#define OF_BENT  (OF_BLP + 12)            // 12
#define OF_SLP   (OF_BENT + 12)           // 68
#define OF_SENT  (OF_SLP + 68)            // 68
#define OF_SKL   (OF_SENT + 68)           // 68
#define OF_SKF   (OF_SKL + 68)            // 16
#define OF_IREG  (OF_SKF + 16)
#define SMEM_FLOATS (OF_IREG + 80)
#define SMEM_BYTES  (SMEM_FLOATS * 4)
#define IO_LKEY  0
#define IO_KB    24
#define IO_KS    48

#define FMA2(acc, w, x) \
    asm("fma.rn.f32x2 %0, %1, %2, %0;" : "+l"(acc) : "l"(w), "l"(x))

__device__ __forceinline__ float lo32(u64 v) { return __uint_as_float((unsigned)v); }
__device__ __forceinline__ float hi32(u64 v) { return __uint_as_float((unsigned)(v >> 32)); }

__device__ __forceinline__ unsigned rotl32(unsigned x, int r) {
    return (x << r) | (x >> (32 - r));
}

__device__ __forceinline__ void tf2x32(unsigned k0, unsigned k1,
                                       unsigned x0, unsigned x1,
                                       unsigned &o0, unsigned &o1) {
    const unsigned ks2 = k0 ^ k1 ^ 0x1BD11BDAu;
    x0 += k0; x1 += k1;
    x0+=x1; x1=rotl32(x1,13); x1^=x0;
    x0+=x1; x1=rotl32(x1,15); x1^=x0;
    x0+=x1; x1=rotl32(x1,26); x1^=x0;
    x0+=x1; x1=rotl32(x1, 6); x1^=x0;
    x0+=k1; x1+=ks2+1u;
    x0+=x1; x1=rotl32(x1,17); x1^=x0;
    x0+=x1; x1=rotl32(x1,29); x1^=x0;
    x0+=x1; x1=rotl32(x1,16); x1^=x0;
    x0+=x1; x1=rotl32(x1,24); x1^=x0;
    x0+=ks2; x1+=k0+2u;
    x0+=x1; x1=rotl32(x1,13); x1^=x0;
    x0+=x1; x1=rotl32(x1,15); x1^=x0;
    x0+=x1; x1=rotl32(x1,26); x1^=x0;
    x0+=x1; x1=rotl32(x1, 6); x1^=x0;
    x0+=k0; x1+=k1+3u;
    x0+=x1; x1=rotl32(x1,17); x1^=x0;
    x0+=x1; x1=rotl32(x1,29); x1^=x0;
    x0+=x1; x1=rotl32(x1,16); x1^=x0;
    x0+=x1; x1=rotl32(x1,24); x1^=x0;
    x0+=k1; x1+=ks2+4u;
    x0+=x1; x1=rotl32(x1,13); x1^=x0;
    x0+=x1; x1=rotl32(x1,15); x1^=x0;
    x0+=x1; x1=rotl32(x1,26); x1^=x0;
    x0+=x1; x1=rotl32(x1, 6); x1^=x0;
    x0+=ks2; x1+=k0+5u;
    o0 = x0; o1 = x1;
}

__device__ __forceinline__ unsigned rbits32(unsigned k0, unsigned k1, int idx) {
    unsigned o0, o1;
    tf2x32(k0, k1, 0u, (unsigned)idx, o0, o1);
    return o0 ^ o1;
}

__device__ __forceinline__ float gumbel_from_bits(unsigned bits) {
    const float TINY = 1.17549435e-38f;
    float f = __uint_as_float(0x3f800000u | (bits >> 9)) - 1.0f;
    float u = fmaxf(TINY, f + TINY);
    return -logf(-logf(u));
}

// HW tanh (MUFU.TANH) and sigmoid via tanh identity — hot loop
__device__ __forceinline__ float tapx(float x) {
    float y;
    asm("tanh.approx.f32 %0, %1;" : "=f"(y) : "f"(x));
    return y;
}
__device__ __forceinline__ float sapx(float x) {
    return fmaf(tapx(0.5f * x), 0.5f, 0.5f);
}

__device__ __forceinline__ float dot64p(const ulonglong2* __restrict__ w,
                                        const ulonglong2* __restrict__ v) {
    u64 a0 = 0ull, a1 = 0ull, a2 = 0ull, a3 = 0ull;
#pragma unroll
    for (int k = 0; k < 16; k += 2) {
        ulonglong2 w0 = w[k], w1 = w[k + 1];
        ulonglong2 v0 = v[k], v1 = v[k + 1];
        FMA2(a0, w0.x, v0.x);
        FMA2(a1, w0.y, v0.y);
        FMA2(a2, w1.x, v1.x);
        FMA2(a3, w1.y, v1.y);
    }
    return ((lo32(a0) + hi32(a0)) + (lo32(a1) + hi32(a1)))
         + ((lo32(a2) + hi32(a2)) + (lo32(a3) + hi32(a3)));
}

__device__ __forceinline__ float dot64r(const u64* __restrict__ w,
                                        const ulonglong2* __restrict__ v) {
    u64 a0 = 0ull, a1 = 0ull, a2 = 0ull, a3 = 0ull;
#pragma unroll
    for (int k = 0; k < 16; k += 2) {
        ulonglong2 v0 = v[k], v1 = v[k + 1];
        FMA2(a0, w[2*k],     v0.x);
        FMA2(a1, w[2*k + 1], v0.y);
        FMA2(a2, w[2*k + 2], v1.x);
        FMA2(a3, w[2*k + 3], v1.y);
    }
    return ((lo32(a0) + hi32(a0)) + (lo32(a1) + hi32(a1)))
         + ((lo32(a2) + hi32(a2)) + (lo32(a3) + hi32(a3)));
}

// Epilogue: lane l holds pre-activation for gate (l>>3), row w*8+(l&7).
__device__ __forceinline__ void epi(float acc, float& c,
                                    float* __restrict__ hout,
                                    int l, int rowIdx) {
    int grp = l >> 3, r8 = l & 7;
    float act = (grp == 2) ? tapx(acc) : sapx(acc);
    float ai = __shfl_sync(0xffffffffu, act, r8);
    float af = __shfl_sync(0xffffffffu, act, r8 + 8);
    float ag = __shfl_sync(0xffffffffu, act, r8 + 16);
    float ao = __shfl_sync(0xffffffffu, act, r8 + 24);
    float cn = af * c + ai * ag;
    c = cn;
    float hv = ao * tapx(cn);
    if (l < 8) hout[rowIdx] = hv;
    __syncthreads();
}

__global__ __launch_bounds__(256, 1)
void enas_controller_kernel(const float* __restrict__ g_emb,
                            const float* __restrict__ w_emb,
                            const float* __restrict__ w_soft,
                            const float* __restrict__ w_attn2,
                            const float* __restrict__ v_attn,
                            const float* __restrict__ w_ih0,
                            const float* __restrict__ w_hh0,
                            const float* __restrict__ b_ih0,
                            const float* __restrict__ b_hh0,
                            const float* __restrict__ w_ih1,
                            const float* __restrict__ w_hh1,
                            const float* __restrict__ b_ih1,
                            const float* __restrict__ b_hh1,
                            const int* __restrict__ seed_p,
                            float* __restrict__ out3) {
    extern __shared__ __align__(16) float S[];
    unsigned* SI = (unsigned*)&S[OF_IREG];
    const int t = threadIdx.x;
    const int w = t >> 5, l = t & 31;
    const int grp = l >> 3, r8 = l & 7;
    const int rowIdx = w * 8 + r8;
    const int R = grp * 64 + rowIdx;

    // ---- stage weights into smem ----
    {
        const float4* g0 = (const float4*)w_ih0;
        for (int idx = t; idx < 256*16; idx += 256) {
            int row = idx >> 4, col = idx & 15;
            *(float4*)&S[OF_WI0 + row*PAD + col*4] = __ldg(&g0[idx]);
        }
        const float4* ga = (const float4*)w_attn2;
        for (int idx = t; idx < 64*16; idx += 256) {
            int row = idx >> 4, col = idx & 15;
            *(float4*)&S[OF_WAT2 + row*PAD + col*4] = __ldg(&ga[idx]);
        }
        const float4* gs = (const float4*)w_soft;
        if (t < NB*16) *(float4*)&S[OF_WSOFT + t*4] = __ldg(&gs[t]);
        const float4* ge = (const float4*)w_emb;
        if (t >= 32 && t < 32 + NB*16) *(float4*)&S[OF_WEMB + (t-32)*4] = __ldg(&ge[t-32]);
        if (t >= 128 && t < 144) *(float4*)&S[OF_GEMB + (t-128)*4] = __ldg(&((const float4*)g_emb)[t-128]);
        if (t >= 160 && t < 160 + HID) {
            S[OF_VATTN + t - 160] = __ldg(&v_attn[t - 160]);
            S[OF_H0A + t - 160] = 0.f;
            S[OF_H1A + t - 160] = 0.f;
        }
    }

    // ---- register weights: wh0, wh1, wi1 rows for gate row R ----
    u64 wh0[32], wh1[32], wi1[32];
    {
        const ulonglong2* p0 = (const ulonglong2*)(w_hh0 + R*HID);
        const ulonglong2* p1 = (const ulonglong2*)(w_hh1 + R*HID);
        const ulonglong2* p2 = (const ulonglong2*)(w_ih1 + R*HID);
#pragma unroll
        for (int k = 0; k < 16; k++) {
            ulonglong2 v0 = __ldg(&p0[k]);
            ulonglong2 v1 = __ldg(&p1[k]);
            ulonglong2 v2 = __ldg(&p2[k]);
            wh0[2*k] = v0.x; wh0[2*k + 1] = v0.y;
            wh1[2*k] = v1.x; wh1[2*k + 1] = v1.y;
            wi1[2*k] = v2.x; wi1[2*k + 1] = v2.y;
        }
    }
    const float b0R = __ldg(&b_ih0[R]) + __ldg(&b_hh0[R]);
    const float b1R = __ldg(&b_ih1[R]) + __ldg(&b_hh1[R]);

    // ---- RNG: serial key chain, then keys + all gumbels in parallel ----
    if (t == 0) {
        unsigned k0 = 0u, k1 = (unsigned)seed_p[0];
        for (int lid = 0; lid < N_LAYERS; lid++) {
            SI[IO_LKEY + 2*lid]     = k0;
            SI[IO_LKEY + 2*lid + 1] = k1;
            unsigned a0, a1;
            tf2x32(k0, k1, 0u, 0u, a0, a1);
            k0 = a0; k1 = a1;
        }
    }
    __syncthreads();
    if (t < 24) {
        int lid = t >> 1, which = t & 1;
        unsigned o0, o1;
        tf2x32(SI[IO_LKEY + 2*lid], SI[IO_LKEY + 2*lid + 1], 0u, (unsigned)(1 + which), o0, o1);
        int base = which ? IO_KS : IO_KB;
        SI[base + 2*lid] = o0; SI[base + 2*lid + 1] = o1;
    }
    // ---- P table (t-indexed): P[b][t] = b0R + wi0[R(t),:] . vec_b ----
    {
        const ulonglong2* wrow = (const ulonglong2*)&S[OF_WI0 + R*PAD];
#pragma unroll
        for (int b = 0; b < 7; b++) {
            const ulonglong2* vec = (const ulonglong2*)
                ((b < 6) ? &S[OF_WEMB + b*HID] : &S[OF_GEMB]);
            S[OF_P + b*256 + t] = b0R + dot64p(wrow, vec);
        }
    }
    __syncthreads();
    if (t < 72) {
        int lid = t / NB, j = t % NB;
        S[OF_GUMB + lid*8 + j] =
            gumbel_from_bits(rbits32(SI[IO_KB + 2*lid], SI[IO_KB + 2*lid + 1], j));
    } else if (t < 72 + 132) {
        int f = t - 72;
        int lid = 1;
        while (f >= lid*(lid+1)) lid++;
        int j = f - lid*(lid-1);
        S[OF_GUMS + f] =
            gumbel_from_bits(rbits32(SI[IO_KS + 2*lid], SI[IO_KS + 2*lid + 1], j));
    }
    __syncthreads();

    float c0 = 0.f, c1 = 0.f;
    // carried dots: sbh0 = wh0 . H0A (for ph1), sbh1 = wh1 . H1A (for ph2).
    // Layer 0 state is zero, so the dots would be exactly +0.0.
    float sbh0 = 0.f, sbh1 = 0.f;

#pragma unroll 1
    for (int lid = 0; lid < N_LAYERS; ++lid) {
        // ===== phase 1: call1-cell0 — NO dots (all hoisted) =====
        {
            float acc;
            if (lid < 2) {
                acc = S[OF_P + 6*256 + t] + sbh0;
            } else {
                int nsk = lid - 1;
                float den = 1.0f, ps = 0.f;
                for (int i = 0; i < nsk; i++) {
                    float f = S[OF_SKF + i];
                    den += f;
                    ps = fmaf(f, S[OF_PA + i*256 + t], ps);
                }
                acc = (b0R + __fdividef(ps, den)) + sbh0;
            }
            epi(acc, c0, &S[OF_H0B], l, rowIdx);
        }
        // ===== phase 2: call1-cell1 + hoisted pre4 (wh0 . H0B) =====
        float pre4;
        {
            float sa = dot64r(wi1, (const ulonglong2*)&S[OF_H0B]);
            pre4 = dot64r(wh0, (const ulonglong2*)&S[OF_H0B]);
            float acc = b1R + (sa + sbh1);
            epi(acc, c1, &S[OF_H1B], l, rowIdx);
        }
        // ===== phase 3: logits + sb1b (wh1 . H1B) + argmax + cell0 epi =====
        float sb1b;
        {
            if (t < 64) {
                int j = t >> 3, k0 = t & 7;
                int jc = (j < NB) ? j : 0;
                const float4* wv = (const float4*)&S[OF_WSOFT + jc*HID + k0*8];
                const float4* hv = (const float4*)&S[OF_H1B + k0*8];
                float4 wa = wv[0], wb = wv[1];
                float4 ha = hv[0], hb = hv[1];
                float s = wa.x*ha.x + wa.y*ha.y + wa.z*ha.z + wa.w*ha.w
                        + wb.x*hb.x + wb.y*hb.y + wb.z*hb.z + wb.w*hb.w;
                s += __shfl_down_sync(0xffffffffu, s, 4, 8);
                s += __shfl_down_sync(0xffffffffu, s, 2, 8);
                s += __shfl_down_sync(0xffffffffu, s, 1, 8);
                if (k0 == 0 && j < NB) S[OF_LOGS + lid*8 + j] = s;
            }
            sb1b = dot64r(wh1, (const ulonglong2*)&S[OF_H1B]);
            __syncthreads();

            float4 la = *(const float4*)&S[OF_LOGS + lid*8];
            float4 lb = *(const float4*)&S[OF_LOGS + lid*8 + 4];
            float4 ga = *(const float4*)&S[OF_GUMB + lid*8];
            float4 gb = *(const float4*)&S[OF_GUMB + lid*8 + 4];
            float z0 = la.x + ga.x, z1 = la.y + ga.y, z2 = la.z + ga.z;
            float z3 = la.w + ga.w, z4 = lb.x + gb.x, z5 = lb.y + gb.y;
            int best = 0; float bz = z0;
            if (z1 > bz) { bz = z1; best = 1; }
            if (z2 > bz) { bz = z2; best = 2; }
            if (z3 > bz) { bz = z3; best = 3; }
            if (z4 > bz) { bz = z4; best = 4; }
            if (z5 > bz) { bz = z5; best = 5; }
            float acc = S[OF_P + best*256 + t] + pre4;
            epi(acc, c0, &S[OF_H0A], l, rowIdx);
        }
        // ===== phase 4: call2-cell1 + hoisted sbh0 (wh0 . H0A) =====
        {
            float sa = dot64r(wi1, (const ulonglong2*)&S[OF_H0A]);
            sbh0 = dot64r(wh0, (const ulonglong2*)&S[OF_H0A]);
            float acc = b1R + (sa + sb1b);
            epi(acc, c1, &S[OF_H1A], l, rowIdx);
        }
        // ===== phase 5: anchor: PA + hoisted sbh1 (both read H1A);
        //       warps 6-7 also w2out/AW1 =====
        {
            if (t >= 192) {
                int r = t - 192;
                float v = dot64p((const ulonglong2*)&S[OF_WAT2 + r*PAD],
                                 (const ulonglong2*)&S[OF_H1A]);
                S[OF_W2OUT + r] = v;
                S[OF_AW1 + lid*HID + r] = v;
            }
            float pa = dot64p((const ulonglong2*)&S[OF_WI0 + R*PAD],
                              (const ulonglong2*)&S[OF_H1A]);
            S[OF_PA + lid*256 + t] = pa;
            sbh1 = dot64r(wh1, (const ulonglong2*)&S[OF_H1A]);
            __syncthreads();
        }

        if (lid > 0) {
            // ===== phase 6: attention q + skip flags (16 thr/row) =====
            if (t < 192) {
                int r = t >> 4, k0 = t & 15;
                int rc = (r < lid) ? r : 0;
                float s = 0.f;
#pragma unroll
                for (int k = 0; k < 4; k++) {
                    int j = k0 + 16*k;
                    s += tapx(S[OF_AW1 + rc*HID + j] + S[OF_W2OUT + j]) * S[OF_VATTN + j];
                }
                s += __shfl_down_sync(0xffffffffu, s, 8, 16);
                s += __shfl_down_sync(0xffffffffu, s, 4, 16);
                s += __shfl_down_sync(0xffffffffu, s, 2, 16);
                s += __shfl_down_sync(0xffffffffu, s, 1, 16);
                if (k0 == 0 && r < lid) {
                    S[OF_QVS + lid*16 + r] = s;
                    float l0 = 1.5f * tapx(s);
                    float g0 = S[OF_GUMS + lid*(lid-1) + 2*r];
                    float g1 = S[OF_GUMS + lid*(lid-1) + 2*r + 1];
                    S[OF_SKF + r] = ((-l0) + g1 > l0 + g0) ? 1.0f : 0.0f;
                }
            }
            __syncthreads();
        }
    }

    // ===== deferred stats (once) =====
    if (t < 12) {
        float lv[NB];
#pragma unroll
        for (int j = 0; j < NB; j++) lv[j] = S[OF_LOGS + t*8 + j];
        float m = lv[0];
#pragma unroll
        for (int j = 1; j < NB; j++) m = fmaxf(m, lv[j]);
        float s = 0.f;
#pragma unroll
        for (int j = 0; j < NB; j++) s += __expf(lv[j] - m);
        float lse = __logf(s);
        int best = 0;
        float bz = lv[0] + S[OF_GUMB + t*8];
#pragma unroll
        for (int j = 1; j < NB; j++) {
            float z = lv[j] + S[OF_GUMB + t*8 + j];
            if (z > bz) { bz = z; best = j; }
        }
        S[OF_BLP + t] = (lv[best] - m) - lse;
        float ent = 0.f;
#pragma unroll
        for (int j = 0; j < NB; j++) {
            float lp = (lv[j] - m) - lse;
            ent -= __expf(lp) * lp;
        }
        S[OF_BENT + t] = ent;
    } else if (t >= 64 && t < 64 + 66) {
        int f = t - 64;
        int lid = 1;
        while (f >= (lid*(lid+1)) >> 1) lid++;
        int r = f - ((lid*(lid-1)) >> 1);
        float q = S[OF_QVS + lid*16 + r];
        float l0 = 1.5f * tapx(q);         // identical op to the in-loop decision
        float l1 = -l0;
        float g0 = S[OF_GUMS + lid*(lid-1) + 2*r];
        float g1 = S[OF_GUMS + lid*(lid-1) + 2*r + 1];
        float m = fmaxf(l0, l1);
        float lsr = __logf(__expf(l0 - m) + __expf(l1 - m));
        float lp0 = (l0 - m) - lsr;
        float lp1 = (l1 - m) - lsr;
        S[OF_SLP + f]  = (l1 + g1 > l0 + g0) ? lp1 : lp0;
        S[OF_SENT + f] = -(__expf(lp0)*lp0 + __expf(lp1)*lp1);
        float s0 = __fdividef(1.0f, 1.0f + __expf(-l0));
        float s1 = __fdividef(1.0f, 1.0f + __expf(-l1));
        S[OF_SKL + f] = s0 * __logf(__fdividef(s0, 0.8f))
                      + s1 * __logf(__fdividef(s1, 0.8f));
    }
    __syncthreads();

    if (t < 32) {
        float s1 = 0.f, s2 = 0.f, s3 = 0.f;
        for (int i = t; i < 12; i += 32) { s1 += S[OF_BLP + i]; s2 += S[OF_BENT + i]; }
        for (int i = t; i < 66; i += 32) {
            s1 += S[OF_SLP + i]; s2 += S[OF_SENT + i]; s3 += S[OF_SKL + i];
        }
#pragma unroll
        for (int off = 16; off > 0; off >>= 1) {
            s1 += __shfl_down_sync(0xffffffffu, s1, off);
            s2 += __shfl_down_sync(0xffffffffu, s2, off);
            s3 += __shfl_down_sync(0xffffffffu, s3, off);
        }
        if (t == 0) {
            out3[0] = s1;
            out3[1] = s2;
            out3[2] = s3;
        }
    }
}

extern "C" void kernel_launch(void* const* d_in, const int* in_sizes, int n_in,
                              void* d_out, int out_size) {
    const float* g_emb   = (const float*)d_in[0];
    const float* w_emb   = (const float*)d_in[1];
    const float* w_soft  = (const float*)d_in[2];
    const float* w_attn2 = (const float*)d_in[3];
    const float* v_attn  = (const float*)d_in[4];
    const float* w_ih0   = (const float*)d_in[5];
    const float* w_hh0   = (const float*)d_in[6];
    const float* b_ih0   = (const float*)d_in[7];
    const float* b_hh0   = (const float*)d_in[8];
    const float* w_ih1   = (const float*)d_in[9];
    const float* w_hh1   = (const float*)d_in[10];
    const float* b_ih1   = (const float*)d_in[11];
    const float* b_hh1   = (const float*)d_in[12];
    const int*   seed    = (const int*)d_in[13];

    cudaFuncSetAttribute(enas_controller_kernel,
                         cudaFuncAttributeMaxDynamicSharedMemorySize, SMEM_BYTES);
    enas_controller_kernel<<<1, 256, SMEM_BYTES>>>(
        g_emb, w_emb, w_soft, w_attn2, v_attn,
        w_ih0, w_hh0, b_ih0, b_hh0,
        w_ih1, w_hh1, b_ih1, b_hh1,
        seed, (float*)d_out);
}

// round 17
// speedup vs baseline: 1.2199x; 1.0014x over previous
#include <cuda_runtime.h>

// ============================================================================
// EnasController R17: R16 base (47.1us) + post-barrier chain cuts in ph3:
// P table preloaded to registers (dependent LDS after argmax -> SEL chain),
// GUMB preloaded before the barrier, tree argmax. All bitwise-identical.
// ============================================================================

#define N_LAYERS 12
#define NB 6
#define HID 64
#define PAD 68

typedef unsigned long long u64;

// ---- shared memory layout (float offsets) ----
#define OF_WI0   0                        // 256*68
#define OF_WAT2  (OF_WI0 + 256*PAD)       // 64*68
#define OF_WSOFT (OF_WAT2 + 64*PAD)       // 384
#define OF_VATTN (OF_WSOFT + 384)         // 64
#define OF_WEMB  (OF_VATTN + 64)          // 384
#define OF_GEMB  (OF_WEMB + 384)          // 64
#define OF_P     (OF_GEMB + 64)           // 7*256  (t-indexed)
#define OF_PA    (OF_P + 7*256)           // 12*256 (t-indexed)
#define OF_H0A   (OF_PA + 12*256)
#define OF_H0B   (OF_H0A + 64)
#define OF_H1A   (OF_H0B + 64)
#define OF_H1B   (OF_H1A + 64)
#define OF_AW1   (OF_H1B + 64)            // 12*64
#define OF_W2OUT (OF_AW1 + 768)           // 64
#define OF_QVS   (OF_W2OUT + 64)          // 12*16
#define OF_LOGS  (OF_QVS + 192)           // 12*8
#define OF_GUMB  (OF_LOGS + 96)           // 12*8 (stride 8)
#define OF_GUMS  (OF_GUMB + 96)           // 136
#define OF_BLP   (OF_GUMS + 136)          // 12
#define OF_BENT  (OF_BLP + 12)            // 12
#define OF_SLP   (OF_BENT + 12)           // 68
#define OF_SENT  (OF_SLP + 68)            // 68
#define OF_SKL   (OF_SENT + 68)           // 68
#define OF_SKF   (OF_SKL + 68)            // 16
#define OF_IREG  (OF_SKF + 16)
#define SMEM_FLOATS (OF_IREG + 80)
#define SMEM_BYTES  (SMEM_FLOATS * 4)
#define IO_LKEY  0
#define IO_KB    24
#define IO_KS    48

#define FMA2(acc, w, x) \
    asm("fma.rn.f32x2 %0, %1, %2, %0;" : "+l"(acc) : "l"(w), "l"(x))

__device__ __forceinline__ float lo32(u64 v) { return __uint_as_float((unsigned)v); }
__device__ __forceinline__ float hi32(u64 v) { return __uint_as_float((unsigned)(v >> 32)); }

__device__ __forceinline__ unsigned rotl32(unsigned x, int r) {
    return (x << r) | (x >> (32 - r));
}

__device__ __forceinline__ void tf2x32(unsigned k0, unsigned k1,
                                       unsigned x0, unsigned x1,
                                       unsigned &o0, unsigned &o1) {
    const unsigned ks2 = k0 ^ k1 ^ 0x1BD11BDAu;
    x0 += k0; x1 += k1;
    x0+=x1; x1=rotl32(x1,13); x1^=x0;
    x0+=x1; x1=rotl32(x1,15); x1^=x0;
    x0+=x1; x1=rotl32(x1,26); x1^=x0;
    x0+=x1; x1=rotl32(x1, 6); x1^=x0;
    x0+=k1; x1+=ks2+1u;
    x0+=x1; x1=rotl32(x1,17); x1^=x0;
    x0+=x1; x1=rotl32(x1,29); x1^=x0;
    x0+=x1; x1=rotl32(x1,16); x1^=x0;
    x0+=x1; x1=rotl32(x1,24); x1^=x0;
    x0+=ks2; x1+=k0+2u;
    x0+=x1; x1=rotl32(x1,13); x1^=x0;
    x0+=x1; x1=rotl32(x1,15); x1^=x0;
    x0+=x1; x1=rotl32(x1,26); x1^=x0;
    x0+=x1; x1=rotl32(x1, 6); x1^=x0;
    x0+=k0; x1+=k1+3u;
    x0+=x1; x1=rotl32(x1,17); x1^=x0;
    x0+=x1; x1=rotl32(x1,29); x1^=x0;
    x0+=x1; x1=rotl32(x1,16); x1^=x0;
    x0+=x1; x1=rotl32(x1,24); x1^=x0;
    x0+=k1; x1+=ks2+4u;
    x0+=x1; x1=rotl32(x1,13); x1^=x0;
    x0+=x1; x1=rotl32(x1,15); x1^=x0;
    x0+=x1; x1=rotl32(x1,26); x1^=x0;
    x0+=x1; x1=rotl32(x1, 6); x1^=x0;
    x0+=ks2; x1+=k0+5u;
    o0 = x0; o1 = x1;
}

__device__ __forceinline__ unsigned rbits32(unsigned k0, unsigned k1, int idx) {
    unsigned o0, o1;
    tf2x32(k0, k1, 0u, (unsigned)idx, o0, o1);
    return o0 ^ o1;
}

__device__ __forceinline__ float gumbel_from_bits(unsigned bits) {
    const float TINY = 1.17549435e-38f;
    float f = __uint_as_float(0x3f800000u | (bits >> 9)) - 1.0f;
    float u = fmaxf(TINY, f + TINY);
    return -logf(-logf(u));
}

// HW tanh (MUFU.TANH) and sigmoid via tanh identity — hot loop
__device__ __forceinline__ float tapx(float x) {
    float y;
    asm("tanh.approx.f32 %0, %1;" : "=f"(y) : "f"(x));
    return y;
}
__device__ __forceinline__ float sapx(float x) {
    return fmaf(tapx(0.5f * x), 0.5f, 0.5f);
}

__device__ __forceinline__ float dot64p(const ulonglong2* __restrict__ w,
                                        const ulonglong2* __restrict__ v) {
    u64 a0 = 0ull, a1 = 0ull, a2 = 0ull, a3 = 0ull;
#pragma unroll
    for (int k = 0; k < 16; k += 2) {
        ulonglong2 w0 = w[k], w1 = w[k + 1];
        ulonglong2 v0 = v[k], v1 = v[k + 1];
        FMA2(a0, w0.x, v0.x);
        FMA2(a1, w0.y, v0.y);
        FMA2(a2, w1.x, v1.x);
        FMA2(a3, w1.y, v1.y);
    }
    return ((lo32(a0) + hi32(a0)) + (lo32(a1) + hi32(a1)))
         + ((lo32(a2) + hi32(a2)) + (lo32(a3) + hi32(a3)));
}

__device__ __forceinline__ float dot64r(const u64* __restrict__ w,
                                        const ulonglong2* __restrict__ v) {
    u64 a0 = 0ull, a1 = 0ull, a2 = 0ull, a3 = 0ull;
#pragma unroll
    for (int k = 0; k < 16; k += 2) {
        ulonglong2 v0 = v[k], v1 = v[k + 1];
        FMA2(a0, w[2*k],     v0.x);
        FMA2(a1, w[2*k + 1], v0.y);
        FMA2(a2, w[2*k + 2], v1.x);
        FMA2(a3, w[2*k + 3], v1.y);
    }
    return ((lo32(a0) + hi32(a0)) + (lo32(a1) + hi32(a1)))
         + ((lo32(a2) + hi32(a2)) + (lo32(a3) + hi32(a3)));
}

// Epilogue: lane l holds pre-activation for gate (l>>3), row w*8+(l&7).
__device__ __forceinline__ void epi(float acc, float& c,
                                    float* __restrict__ hout,
                                    int l, int rowIdx) {
    int grp = l >> 3, r8 = l & 7;
    float act = (grp == 2) ? tapx(acc) : sapx(acc);
    float ai = __shfl_sync(0xffffffffu, act, r8);
    float af = __shfl_sync(0xffffffffu, act, r8 + 8);
    float ag = __shfl_sync(0xffffffffu, act, r8 + 16);
    float ao = __shfl_sync(0xffffffffu, act, r8 + 24);
    float cn = af * c + ai * ag;
    c = cn;
    float hv = ao * tapx(cn);
    if (l < 8) hout[rowIdx] = hv;
    __syncthreads();
}

__global__ __launch_bounds__(256, 1)
void enas_controller_kernel(const float* __restrict__ g_emb,
                            const float* __restrict__ w_emb,
                            const float* __restrict__ w_soft,
                            const float* __restrict__ w_attn2,
                            const float* __restrict__ v_attn,
                            const float* __restrict__ w_ih0,
                            const float* __restrict__ w_hh0,
                            const float* __restrict__ b_ih0,
                            const float* __restrict__ b_hh0,
                            const float* __restrict__ w_ih1,
                            const float* __restrict__ w_hh1,
                            const float* __restrict__ b_ih1,
                            const float* __restrict__ b_hh1,
                            const int* __restrict__ seed_p,
                            float* __restrict__ out3) {
    extern __shared__ __align__(16) float S[];
    unsigned* SI = (unsigned*)&S[OF_IREG];
    const int t = threadIdx.x;
    const int w = t >> 5, l = t & 31;
    const int grp = l >> 3, r8 = l & 7;
    const int rowIdx = w * 8 + r8;
    const int R = grp * 64 + rowIdx;

    // ---- stage weights into smem ----
    {
        const float4* g0 = (const float4*)w_ih0;
        for (int idx = t; idx < 256*16; idx += 256) {
            int row = idx >> 4, col = idx & 15;
            *(float4*)&S[OF_WI0 + row*PAD + col*4] = __ldg(&g0[idx]);
        }
        const float4* ga = (const float4*)w_attn2;
        for (int idx = t; idx < 64*16; idx += 256) {
            int row = idx >> 4, col = idx & 15;
            *(float4*)&S[OF_WAT2 + row*PAD + col*4] = __ldg(&ga[idx]);
        }
        const float4* gs = (const float4*)w_soft;
        if (t < NB*16) *(float4*)&S[OF_WSOFT + t*4] = __ldg(&gs[t]);
        const float4* ge = (const float4*)w_emb;
        if (t >= 32 && t < 32 + NB*16) *(float4*)&S[OF_WEMB + (t-32)*4] = __ldg(&ge[t-32]);
        if (t >= 128 && t < 144) *(float4*)&S[OF_GEMB + (t-128)*4] = __ldg(&((const float4*)g_emb)[t-128]);
        if (t >= 160 && t < 160 + HID) {
            S[OF_VATTN + t - 160] = __ldg(&v_attn[t - 160]);
            S[OF_H0A + t - 160] = 0.f;
            S[OF_H1A + t - 160] = 0.f;
        }
    }

    // ---- register weights: wh0, wh1, wi1 rows for gate row R ----
    u64 wh0[32], wh1[32], wi1[32];
    {
        const ulonglong2* p0 = (const ulonglong2*)(w_hh0 + R*HID);
        const ulonglong2* p1 = (const ulonglong2*)(w_hh1 + R*HID);
        const ulonglong2* p2 = (const ulonglong2*)(w_ih1 + R*HID);
#pragma unroll
        for (int k = 0; k < 16; k++) {
            ulonglong2 v0 = __ldg(&p0[k]);
            ulonglong2 v1 = __ldg(&p1[k]);
            ulonglong2 v2 = __ldg(&p2[k]);
            wh0[2*k] = v0.x; wh0[2*k + 1] = v0.y;
            wh1[2*k] = v1.x; wh1[2*k + 1] = v1.y;
            wi1[2*k] = v2.x; wi1[2*k + 1] = v2.y;
        }
    }
    const float b0R = __ldg(&b_ih0[R]) + __ldg(&b_hh0[R]);
    const float b1R = __ldg(&b_ih1[R]) + __ldg(&b_hh1[R]);

    // ---- RNG: serial key chain, then keys + all gumbels in parallel ----
    if (t == 0) {
        unsigned k0 = 0u, k1 = (unsigned)seed_p[0];
        for (int lid = 0; lid < N_LAYERS; lid++) {
            SI[IO_LKEY + 2*lid]     = k0;
            SI[IO_LKEY + 2*lid + 1] = k1;
            unsigned a0, a1;
            tf2x32(k0, k1, 0u, 0u, a0, a1);
            k0 = a0; k1 = a1;
        }
    }
    __syncthreads();
    if (t < 24) {
        int lid = t >> 1, which = t & 1;
        unsigned o0, o1;
        tf2x32(SI[IO_LKEY + 2*lid], SI[IO_LKEY + 2*lid + 1], 0u, (unsigned)(1 + which), o0, o1);
        int base = which ? IO_KS : IO_KB;
        SI[base + 2*lid] = o0; SI[base + 2*lid + 1] = o1;
    }
    // ---- P table (t-indexed): P[b][t] = b0R + wi0[R(t),:] . vec_b ----
    {
        const ulonglong2* wrow = (const ulonglong2*)&S[OF_WI0 + R*PAD];
#pragma unroll
        for (int b = 0; b < 7; b++) {
            const ulonglong2* vec = (const ulonglong2*)
                ((b < 6) ? &S[OF_WEMB + b*HID] : &S[OF_GEMB]);
            S[OF_P + b*256 + t] = b0R + dot64p(wrow, vec);
        }
    }
    __syncthreads();
    if (t < 72) {
        int lid = t / NB, j = t % NB;
        S[OF_GUMB + lid*8 + j] =
            gumbel_from_bits(rbits32(SI[IO_KB + 2*lid], SI[IO_KB + 2*lid + 1], j));
    } else if (t < 72 + 132) {
        int f = t - 72;
        int lid = 1;
        while (f >= lid*(lid+1)) lid++;
        int j = f - lid*(lid-1);
        S[OF_GUMS + f] =
            gumbel_from_bits(rbits32(SI[IO_KS + 2*lid], SI[IO_KS + 2*lid + 1], j));
    }
    __syncthreads();

    // ---- preload the 7 P values for this thread into registers (static) ----
    float P0 = S[OF_P + 0*256 + t];
    float P1 = S[OF_P + 1*256 + t];
    float P2 = S[OF_P + 2*256 + t];
    float P3 = S[OF_P + 3*256 + t];
    float P4 = S[OF_P + 4*256 + t];
    float P5 = S[OF_P + 5*256 + t];
    float P6 = S[OF_P + 6*256 + t];

    float c0 = 0.f, c1 = 0.f;
    float sbh0 = 0.f, sbh1 = 0.f;   // carried dots (layer 0: exactly +0.0)

#pragma unroll 1
    for (int lid = 0; lid < N_LAYERS; ++lid) {
        // ===== phase 1: call1-cell0 — NO dots (all hoisted) =====
        {
            float acc;
            if (lid < 2) {
                acc = P6 + sbh0;
            } else {
                int nsk = lid - 1;
                float den = 1.0f, ps = 0.f;
                for (int i = 0; i < nsk; i++) {
                    float f = S[OF_SKF + i];
                    den += f;
                    ps = fmaf(f, S[OF_PA + i*256 + t], ps);
                }
                acc = (b0R + __fdividef(ps, den)) + sbh0;
            }
            epi(acc, c0, &S[OF_H0B], l, rowIdx);
        }
        // ===== phase 2: call1-cell1 + hoisted pre4 (wh0 . H0B) =====
        float pre4;
        {
            float sa = dot64r(wi1, (const ulonglong2*)&S[OF_H0B]);
            pre4 = dot64r(wh0, (const ulonglong2*)&S[OF_H0B]);
            float acc = b1R + (sa + sbh1);
            epi(acc, c1, &S[OF_H1B], l, rowIdx);
        }
        // ===== phase 3: logits + sb1b + argmax(tree) + cell0 epi =====
        float sb1b;
        {
            if (t < 64) {
                int j = t >> 3, k0 = t & 7;
                int jc = (j < NB) ? j : 0;
                const float4* wv = (const float4*)&S[OF_WSOFT + jc*HID + k0*8];
                const float4* hv = (const float4*)&S[OF_H1B + k0*8];
                float4 wa = wv[0], wb = wv[1];
                float4 ha = hv[0], hb = hv[1];
                float s = wa.x*ha.x + wa.y*ha.y + wa.z*ha.z + wa.w*ha.w
                        + wb.x*hb.x + wb.y*hb.y + wb.z*hb.z + wb.w*hb.w;
                s += __shfl_down_sync(0xffffffffu, s, 4, 8);
                s += __shfl_down_sync(0xffffffffu, s, 2, 8);
                s += __shfl_down_sync(0xffffffffu, s, 1, 8);
                if (k0 == 0 && j < NB) S[OF_LOGS + lid*8 + j] = s;
            }
            // GUMB preload (static) overlapped with the dot, BEFORE the barrier
            float4 gq0 = *(const float4*)&S[OF_GUMB + lid*8];
            float4 gq1 = *(const float4*)&S[OF_GUMB + lid*8 + 4];
            sb1b = dot64r(wh1, (const ulonglong2*)&S[OF_H1B]);
            __syncthreads();

            float4 la = *(const float4*)&S[OF_LOGS + lid*8];
            float4 lb = *(const float4*)&S[OF_LOGS + lid*8 + 4];
            float z0 = la.x + gq0.x, z1 = la.y + gq0.y, z2 = la.z + gq0.z;
            float z3 = la.w + gq0.w, z4 = lb.x + gq1.x, z5 = lb.y + gq1.y;
            // tree argmax, first-max-on-tie (right wins only if strictly greater)
            float m01 = z0;  int i01 = 0;  if (z1 > m01) { m01 = z1; i01 = 1; }
            float m23 = z2;  int i23 = 2;  if (z3 > m23) { m23 = z3; i23 = 3; }
            float m45 = z4;  int i45 = 4;  if (z5 > m45) { m45 = z5; i45 = 5; }
            float m03 = m01; int i03 = i01; if (m23 > m03) { m03 = m23; i03 = i23; }
            int best = i03;  if (m45 > m03) best = i45;
            // P select from registers (no dependent LDS)
            float pb = P0;
            pb = (best == 1) ? P1 : pb;
            pb = (best == 2) ? P2 : pb;
            pb = (best == 3) ? P3 : pb;
            pb = (best == 4) ? P4 : pb;
            pb = (best == 5) ? P5 : pb;
            float acc = pb + pre4;
            epi(acc, c0, &S[OF_H0A], l, rowIdx);
        }
        // ===== phase 4: call2-cell1 + hoisted sbh0 (wh0 . H0A) =====
        {
            float sa = dot64r(wi1, (const ulonglong2*)&S[OF_H0A]);
            sbh0 = dot64r(wh0, (const ulonglong2*)&S[OF_H0A]);
            float acc = b1R + (sa + sb1b);
            epi(acc, c1, &S[OF_H1A], l, rowIdx);
        }
        // ===== phase 5: anchor: PA + hoisted sbh1; warps 6-7 also w2out/AW1 =====
        {
            if (t >= 192) {
                int r = t - 192;
                float v = dot64p((const ulonglong2*)&S[OF_WAT2 + r*PAD],
                                 (const ulonglong2*)&S[OF_H1A]);
                S[OF_W2OUT + r] = v;
                S[OF_AW1 + lid*HID + r] = v;
            }
            float pa = dot64p((const ulonglong2*)&S[OF_WI0 + R*PAD],
                              (const ulonglong2*)&S[OF_H1A]);
            S[OF_PA + lid*256 + t] = pa;
            sbh1 = dot64r(wh1, (const ulonglong2*)&S[OF_H1A]);
            __syncthreads();
        }

        if (lid > 0) {
            // ===== phase 6: attention q + skip flags (16 thr/row) =====
            if (t < 192) {
                int r = t >> 4, k0 = t & 15;
                int rc = (r < lid) ? r : 0;
                float s = 0.f;
#pragma unroll
                for (int k = 0; k < 4; k++) {
                    int j = k0 + 16*k;
                    s += tapx(S[OF_AW1 + rc*HID + j] + S[OF_W2OUT + j]) * S[OF_VATTN + j];
                }
                s += __shfl_down_sync(0xffffffffu, s, 8, 16);
                s += __shfl_down_sync(0xffffffffu, s, 4, 16);
                s += __shfl_down_sync(0xffffffffu, s, 2, 16);
                s += __shfl_down_sync(0xffffffffu, s, 1, 16);
                if (k0 == 0 && r < lid) {
                    S[OF_QVS + lid*16 + r] = s;
                    float l0 = 1.5f * tapx(s);
                    float g0 = S[OF_GUMS + lid*(lid-1) + 2*r];
                    float g1 = S[OF_GUMS + lid*(lid-1) + 2*r + 1];
                    S[OF_SKF + r] = ((-l0) + g1 > l0 + g0) ? 1.0f : 0.0f;
                }
            }
            __syncthreads();
        }
    }

    // ===== deferred stats (once) =====
    if (t < 12) {
        float lv[NB];
#pragma unroll
        for (int j = 0; j < NB; j++) lv[j] = S[OF_LOGS + t*8 + j];
        float m = lv[0];
#pragma unroll
        for (int j = 1; j < NB; j++) m = fmaxf(m, lv[j]);
        float s = 0.f;
#pragma unroll
        for (int j = 0; j < NB; j++) s += __expf(lv[j] - m);
        float lse = __logf(s);
        int best = 0;
        float bz = lv[0] + S[OF_GUMB + t*8];
#pragma unroll
        for (int j = 1; j < NB; j++) {
            float z = lv[j] + S[OF_GUMB + t*8 + j];
            if (z > bz) { bz = z; best = j; }
        }
        S[OF_BLP + t] = (lv[best] - m) - lse;
        float ent = 0.f;
#pragma unroll
        for (int j = 0; j < NB; j++) {
            float lp = (lv[j] - m) - lse;
            ent -= __expf(lp) * lp;
        }
        S[OF_BENT + t] = ent;
    } else if (t >= 64 && t < 64 + 66) {
        int f = t - 64;
        int lid = 1;
        while (f >= (lid*(lid+1)) >> 1) lid++;
        int r = f - ((lid*(lid-1)) >> 1);
        float q = S[OF_QVS + lid*16 + r];
        float l0 = 1.5f * tapx(q);         // identical op to the in-loop decision
        float l1 = -l0;
        float g0 = S[OF_GUMS + lid*(lid-1) + 2*r];
        float g1 = S[OF_GUMS + lid*(lid-1) + 2*r + 1];
        float m = fmaxf(l0, l1);
        float lsr = __logf(__expf(l0 - m) + __expf(l1 - m));
        float lp0 = (l0 - m) - lsr;
        float lp1 = (l1 - m) - lsr;
        S[OF_SLP + f]  = (l1 + g1 > l0 + g0) ? lp1 : lp0;
        S[OF_SENT + f] = -(__expf(lp0)*lp0 + __expf(lp1)*lp1);
        float s0 = __fdividef(1.0f, 1.0f + __expf(-l0));
        float s1 = __fdividef(1.0f, 1.0f + __expf(-l1));
        S[OF_SKL + f] = s0 * __logf(__fdividef(s0, 0.8f))
                      + s1 * __logf(__fdividef(s1, 0.8f));
    }
    __syncthreads();

    if (t < 32) {
        float s1 = 0.f, s2 = 0.f, s3 = 0.f;
        for (int i = t; i < 12; i += 32) { s1 += S[OF_BLP + i]; s2 += S[OF_BENT + i]; }
        for (int i = t; i < 66; i += 32) {
            s1 += S[OF_SLP + i]; s2 += S[OF_SENT + i]; s3 += S[OF_SKL + i];
        }
#pragma unroll
        for (int off = 16; off > 0; off >>= 1) {
            s1 += __shfl_down_sync(0xffffffffu, s1, off);
            s2 += __shfl_down_sync(0xffffffffu, s2, off);
            s3 += __shfl_down_sync(0xffffffffu, s3, off);
        }
        if (t == 0) {
            out3[0] = s1;
            out3[1] = s2;
            out3[2] = s3;
        }
    }
}

extern "C" void kernel_launch(void* const* d_in, const int* in_sizes, int n_in,
                              void* d_out, int out_size) {
    const float* g_emb   = (const float*)d_in[0];
    const float* w_emb   = (const float*)d_in[1];
    const float* w_soft  = (const float*)d_in[2];
    const float* w_attn2 = (const float*)d_in[3];
    const float* v_attn  = (const float*)d_in[4];
    const float* w_ih0   = (const float*)d_in[5];
    const float* w_hh0   = (const float*)d_in[6];
    const float* b_ih0   = (const float*)d_in[7];
    const float* b_hh0   = (const float*)d_in[8];
    const float* w_ih1   = (const float*)d_in[9];
    const float* w_hh1   = (const float*)d_in[10];
    const float* b_ih1   = (const float*)d_in[11];
    const float* b_hh1   = (const float*)d_in[12];
    const int*   seed    = (const int*)d_in[13];

    cudaFuncSetAttribute(enas_controller_kernel,
                         cudaFuncAttributeMaxDynamicSharedMemorySize, SMEM_BYTES);
    enas_controller_kernel<<<1, 256, SMEM_BYTES>>>(
        g_emb, w_emb, w_soft, w_attn2, v_attn,
        w_ih0, w_hh0, b_ih0, b_hh0,
        w_ih1, w_hh1, b_ih1, b_hh1,
        seed, (float*)d_out);
}